// round 3
// baseline (speedup 1.0000x reference)
#include <cuda_runtime.h>
#include <cuda_bf16.h>
#include <math.h>

// ---------------- problem constants ----------------
#define NB    8          // batch
#define CCH   640        // channels
#define HW    1024       // 32*32
#define NTOK  (NB*HW)    // 8192 tokens
#define NH    8          // heads
#define DH    80         // head dim
#define SCTX  77         // context length
#define DCTX  512
#define FF    5120       // lin1 out
#define FFH   2560
#define GRP   32
#define CPG   (CCH/GRP)  // 20

// ---------------- scratch (static device memory; no cudaMalloc allowed) ----
__device__ float g_X [ (long)NTOK * CCH ];          // running x  [8192,640]
__device__ float g_A [ (long)NTOK * FF  ];          // qkv / lin1 out [8192,5120]
__device__ float g_B [ (long)NTOK * FFH ];          // ln out / attn out / geglu [8192,2560]
__device__ float g_S [ (long)NB * NH * HW * HW ];   // scores [8,8,1024,1024]
__device__ float g_CK[ (long)NB * SCTX * CCH ];
__device__ float g_CV[ (long)NB * SCTX * CCH ];
__device__ float g_GS[ NB * GRP * 2 ];              // groupnorm mean/rstd

// ================= GroupNorm stats =================
__global__ void gn_stats_k(const float* __restrict__ x, float* __restrict__ st) {
    // block = (n,g); elements are contiguous: 20 channels * 1024 hw
    int n = blockIdx.x >> 5, g = blockIdx.x & 31;
    const float* base = x + ((long)n * CCH + g * CPG) * HW;
    const int CNT = CPG * HW; // 20480
    float s = 0.f, s2 = 0.f;
    for (int i = threadIdx.x; i < CNT; i += 256) {
        float v = base[i]; s += v; s2 += v * v;
    }
    __shared__ float r1[256], r2[256];
    r1[threadIdx.x] = s; r2[threadIdx.x] = s2; __syncthreads();
    for (int st_ = 128; st_ > 0; st_ >>= 1) {
        if (threadIdx.x < st_) { r1[threadIdx.x] += r1[threadIdx.x + st_]; r2[threadIdx.x] += r2[threadIdx.x + st_]; }
        __syncthreads();
    }
    if (threadIdx.x == 0) {
        float mean = r1[0] / (float)CNT;
        float var  = r2[0] / (float)CNT - mean * mean;
        st[blockIdx.x * 2]     = mean;
        st[blockIdx.x * 2 + 1] = rsqrtf(var + 1e-6f);
    }
}

// ======== GroupNorm apply + transpose [n,c,hw] -> [token, c] ========
__global__ void gn_apply_t_k(const float* __restrict__ x, const float* __restrict__ st,
                             const float* __restrict__ gs, const float* __restrict__ gb,
                             float* __restrict__ out) {
    __shared__ float tile[32][33];
    int n = blockIdx.z, c0 = blockIdx.y * 32, hw0 = blockIdx.x * 32;
    int tx = threadIdx.x, ty = threadIdx.y;
#pragma unroll
    for (int j = 0; j < 4; j++) {
        int c = c0 + ty + j * 8;
        float v = x[((long)n * CCH + c) * HW + hw0 + tx];
        int g = c / CPG;
        float mu = st[(n * GRP + g) * 2], r = st[(n * GRP + g) * 2 + 1];
        tile[ty + j * 8][tx] = (v - mu) * r * gs[c] + gb[c];
    }
    __syncthreads();
#pragma unroll
    for (int j = 0; j < 4; j++) {
        int hw = hw0 + ty + j * 8;
        out[((long)n * HW + hw) * CCH + c0 + tx] = tile[tx][ty + j * 8];
    }
}

// ================= LayerNorm (row = token, width 640) =================
__global__ void layernorm_k(const float* __restrict__ X, const float* __restrict__ s,
                            const float* __restrict__ b, float* __restrict__ O) {
    long row = blockIdx.x;
    const float* p = X + row * CCH;
    int tid = threadIdx.x;
    float v[3]; int cnt = 0;
    float sm = 0.f, s2 = 0.f;
    for (int i = tid; i < CCH; i += 256) { float t = p[i]; v[cnt++] = t; sm += t; s2 += t * t; }
    __shared__ float r1[256], r2[256];
    r1[tid] = sm; r2[tid] = s2; __syncthreads();
    for (int st = 128; st > 0; st >>= 1) {
        if (tid < st) { r1[tid] += r1[tid + st]; r2[tid] += r2[tid + st]; }
        __syncthreads();
    }
    float mean = r1[0] / (float)CCH;
    float var  = r2[0] / (float)CCH - mean * mean;
    float rstd = rsqrtf(var + 1e-5f);
    cnt = 0;
    for (int i = tid; i < CCH; i += 256)
        O[row * CCH + i] = (v[cnt++] - mean) * rstd * s[i] + b[i];
}

// ================= big GEMM: C[M,N] = A[M,K] @ op(B) (+bias)(+res) =======
// BT=false: B is [K,N] row-major (w[in,out]).  BT=true: B is [N,K] (w[out,in]).
// permute: write C as [n, o, hw] (token m -> n=m>>10, hw=m&1023); res read at same index.
template<bool BT>
__global__ __launch_bounds__(256) void gemm_big(
    const float* __restrict__ A, const float* __restrict__ B,
    const float* __restrict__ bias, const float* __restrict__ res,
    float* __restrict__ C, int M, int N, int K, int permute) {
    __shared__ float As[16][132];
    __shared__ float Bs[16][68];
    int tid = threadIdx.x;
    int m0 = blockIdx.y * 128, n0 = blockIdx.x * 64;
    int ty = tid >> 4, tx = tid & 15;      // 16x16 thread grid; 8x4 micro-tile
    float acc[8][4] = {};
    for (int k0 = 0; k0 < K; k0 += 16) {
#pragma unroll
        for (int i = 0; i < 8; i++) {       // A tile 128x16
            int lin = tid + i * 256;
            int m = lin >> 4, k = lin & 15;
            float v = 0.f;
            int gm = m0 + m;
            if (gm < M && k0 + k < K) v = A[(long)gm * K + k0 + k];
            As[k][m] = v;
        }
#pragma unroll
        for (int i = 0; i < 4; i++) {       // B tile 16x64
            int lin = tid + i * 256;
            float v = 0.f;
            if (BT) {
                int n = lin >> 4, k = lin & 15;
                int gn = n0 + n;
                if (gn < N && k0 + k < K) v = B[(long)gn * K + k0 + k];
                Bs[k][n] = v;
            } else {
                int k = lin >> 6, n = lin & 63;
                int gn = n0 + n;
                if (gn < N && k0 + k < K) v = B[(long)(k0 + k) * N + gn];
                Bs[k][n] = v;
            }
        }
        __syncthreads();
#pragma unroll
        for (int k = 0; k < 16; k++) {
            float4 a0 = *(const float4*)&As[k][ty * 8];
            float4 a1 = *(const float4*)&As[k][ty * 8 + 4];
            float4 bb = *(const float4*)&Bs[k][tx * 4];
            float a[8] = {a0.x,a0.y,a0.z,a0.w,a1.x,a1.y,a1.z,a1.w};
            float b[4] = {bb.x,bb.y,bb.z,bb.w};
#pragma unroll
            for (int i = 0; i < 8; i++)
#pragma unroll
                for (int j = 0; j < 4; j++) acc[i][j] = fmaf(a[i], b[j], acc[i][j]);
        }
        __syncthreads();
    }
#pragma unroll
    for (int i = 0; i < 8; i++) {
        int gm = m0 + ty * 8 + i;
        if (gm >= M) continue;
#pragma unroll
        for (int j = 0; j < 4; j++) {
            int gn = n0 + tx * 4 + j;
            if (gn >= N) continue;
            float v = acc[i][j];
            if (bias) v += bias[gn];
            long idx;
            if (!permute) idx = (long)gm * N + gn;
            else          idx = ((long)(gm >> 10) * CCH + gn) * HW + (gm & 1023);
            if (res) v += res[idx];
            C[idx] = v;
        }
    }
}

// ========== batched GEMM over z=b*NH+h : C = alpha * A @ op(B) ==========
template<bool BT>
__global__ __launch_bounds__(256) void bgemm(
    const float* __restrict__ Ab, const float* __restrict__ Bb, float* __restrict__ Cb,
    int M, int N, int Kd, int lda, int ldb, int ldc,
    long aB, long aH, long bB, long bH, long cB, long cH, float alpha) {
    int z = blockIdx.z, b = z >> 3, h = z & 7;
    const float* A = Ab + b * aB + h * aH;
    const float* B = Bb + b * bB + h * bH;
    float* C = Cb + b * cB + h * cH;
    __shared__ float As[16][68];
    __shared__ float Bs[16][68];
    int tid = threadIdx.x;
    int m0 = blockIdx.y * 64, n0 = blockIdx.x * 64;
    int ty = tid >> 4, tx = tid & 15;      // 4x4 micro-tile
    float acc[4][4] = {};
    for (int k0 = 0; k0 < Kd; k0 += 16) {
#pragma unroll
        for (int i = 0; i < 4; i++) {       // A tile 64x16
            int lin = tid + i * 256;
            int m = lin >> 4, k = lin & 15;
            float v = 0.f;
            if (m0 + m < M && k0 + k < Kd) v = A[(long)(m0 + m) * lda + k0 + k];
            As[k][m] = v;
        }
#pragma unroll
        for (int i = 0; i < 4; i++) {       // B tile 16x64
            int lin = tid + i * 256;
            float v = 0.f;
            if (BT) {
                int n = lin >> 4, k = lin & 15;
                if (n0 + n < N && k0 + k < Kd) v = B[(long)(n0 + n) * ldb + k0 + k];
                Bs[k][n] = v;
            } else {
                int k = lin >> 6, n = lin & 63;
                if (n0 + n < N && k0 + k < Kd) v = B[(long)(k0 + k) * ldb + n0 + n];
                Bs[k][n] = v;
            }
        }
        __syncthreads();
#pragma unroll
        for (int k = 0; k < 16; k++) {
            float4 av = *(const float4*)&As[k][ty * 4];
            float4 bv = *(const float4*)&Bs[k][tx * 4];
            float a[4] = {av.x,av.y,av.z,av.w};
            float b2[4] = {bv.x,bv.y,bv.z,bv.w};
#pragma unroll
            for (int i = 0; i < 4; i++)
#pragma unroll
                for (int j = 0; j < 4; j++) acc[i][j] = fmaf(a[i], b2[j], acc[i][j]);
        }
        __syncthreads();
    }
#pragma unroll
    for (int i = 0; i < 4; i++) {
        int gm = m0 + ty * 4 + i;
        if (gm >= M) continue;
#pragma unroll
        for (int j = 0; j < 4; j++) {
            int gn = n0 + tx * 4 + j;
            if (gn >= N) continue;
            C[(long)gm * ldc + gn] = alpha * acc[i][j];
        }
    }
}

// ================= row softmax =================
__global__ void softmax_k(float* __restrict__ S, int L) {
    __shared__ float red[128];
    long row = blockIdx.x;
    float* p = S + row * (long)L;
    int tid = threadIdx.x;
    float v[8]; int cnt = 0;
    float mx = -1e30f;
    for (int i = tid; i < L; i += 128) { float t = p[i]; v[cnt++] = t; mx = fmaxf(mx, t); }
    red[tid] = mx; __syncthreads();
    for (int s = 64; s > 0; s >>= 1) { if (tid < s) red[tid] = fmaxf(red[tid], red[tid + s]); __syncthreads(); }
    mx = red[0]; __syncthreads();
    float sum = 0.f;
    for (int c = 0; c < cnt; c++) { v[c] = expf(v[c] - mx); sum += v[c]; }
    red[tid] = sum; __syncthreads();
    for (int s = 64; s > 0; s >>= 1) { if (tid < s) red[tid] += red[tid + s]; __syncthreads(); }
    float inv = 1.f / red[0];
    cnt = 0;
    for (int i = tid; i < L; i += 128) p[i] = v[cnt++] * inv;
}

// ================= GeGLU: out = a * gelu_exact(gate) =================
__global__ void geglu_k(const float* __restrict__ A, float* __restrict__ O) {
    long i = (long)blockIdx.x * 256 + threadIdx.x;
    if (i >= (long)NTOK * FFH) return;
    long row = i / FFH; int col = (int)(i % FFH);
    float a = A[row * FF + col];
    float g = A[row * FF + FFH + col];
    O[i] = a * (0.5f * g * (1.0f + erff(g * 0.70710678118654752f)));
}

// =========================================================================
extern "C" void kernel_launch(void* const* d_in, const int* in_sizes, int n_in,
                              void* d_out, int out_size) {
    const float* x       = (const float*)d_in[0];
    const float* ctx     = (const float*)d_in[1];
    const float* gn_s    = (const float*)d_in[2];
    const float* gn_b    = (const float*)d_in[3];
    const float* conv1_w = (const float*)d_in[4];
    const float* conv1_b = (const float*)d_in[5];
    const float* ln1_s   = (const float*)d_in[6];
    const float* ln1_b   = (const float*)d_in[7];
    const float* sa_in_w = (const float*)d_in[8];
    const float* sa_out_w= (const float*)d_in[9];
    const float* sa_out_b= (const float*)d_in[10];
    const float* ln2_s   = (const float*)d_in[11];
    const float* ln2_b   = (const float*)d_in[12];
    const float* ca_q_w  = (const float*)d_in[13];
    const float* ca_k_w  = (const float*)d_in[14];
    const float* ca_v_w  = (const float*)d_in[15];
    const float* ca_out_w= (const float*)d_in[16];
    const float* ca_out_b= (const float*)d_in[17];
    const float* ln3_s   = (const float*)d_in[18];
    const float* ln3_b   = (const float*)d_in[19];
    const float* lin1_w  = (const float*)d_in[20];
    const float* lin1_b  = (const float*)d_in[21];
    const float* lin2_w  = (const float*)d_in[22];
    const float* lin2_b  = (const float*)d_in[23];
    const float* co_w    = (const float*)d_in[24];
    const float* co_b    = (const float*)d_in[25];
    float* out = (float*)d_out;

    float *pX, *pA, *pB, *pS, *pCK, *pCV, *pGS;
    cudaGetSymbolAddress((void**)&pX,  g_X);
    cudaGetSymbolAddress((void**)&pA,  g_A);
    cudaGetSymbolAddress((void**)&pB,  g_B);
    cudaGetSymbolAddress((void**)&pS,  g_S);
    cudaGetSymbolAddress((void**)&pCK, g_CK);
    cudaGetSymbolAddress((void**)&pCV, g_CV);
    cudaGetSymbolAddress((void**)&pGS, g_GS);

    const float ISQ = 0.11180339887498949f; // 1/sqrt(80)

    // 1) GroupNorm -> token-major (into g_B first 640 cols packed)
    gn_stats_k<<<NB * GRP, 256>>>(x, pGS);
    gn_apply_t_k<<<dim3(32, 20, NB), dim3(32, 8)>>>(x, pGS, gn_s, gn_b, pB);

    // 2) conv1: X = XN @ conv1_w^T + b      (conv1_w is [out,in] -> BT)
    gemm_big<true><<<dim3(CCH / 64, NTOK / 128), 256>>>(pB, conv1_w, conv1_b, nullptr, pX, NTOK, CCH, CCH, 0);

    // 3) self-attention
    layernorm_k<<<NTOK, 256>>>(pX, ln1_s, ln1_b, pB);
    gemm_big<false><<<dim3(3 * CCH / 64, NTOK / 128), 256>>>(pB, sa_in_w, nullptr, nullptr, pA, NTOK, 3 * CCH, CCH, 0);
    // scores = Q K^T / sqrt(dh)
    bgemm<true><<<dim3(16, 16, NB * NH), 256>>>(
        pA, pA + CCH, pS, HW, HW, DH, 3 * CCH, 3 * CCH, HW,
        (long)HW * 3 * CCH, DH, (long)HW * 3 * CCH, DH, (long)NH * HW * HW, (long)HW * HW, ISQ);
    softmax_k<<<NB * NH * HW, 128>>>(pS, HW);
    // O = P V
    bgemm<false><<<dim3(2, 16, NB * NH), 256>>>(
        pS, pA + 2 * CCH, pB, HW, DH, HW, HW, 3 * CCH, CCH,
        (long)NH * HW * HW, (long)HW * HW, (long)HW * 3 * CCH, DH, (long)HW * CCH, DH, 1.0f);
    gemm_big<false><<<dim3(CCH / 64, NTOK / 128), 256>>>(pB, sa_out_w, sa_out_b, pX, pX, NTOK, CCH, CCH, 0);

    // 4) cross-attention
    layernorm_k<<<NTOK, 256>>>(pX, ln2_s, ln2_b, pB);
    gemm_big<false><<<dim3(CCH / 64, NTOK / 128), 256>>>(pB, ca_q_w, nullptr, nullptr, pA, NTOK, CCH, CCH, 0);
    gemm_big<false><<<dim3(CCH / 64, (NB * SCTX + 127) / 128), 256>>>(ctx, ca_k_w, nullptr, nullptr, pCK, NB * SCTX, CCH, DCTX, 0);
    gemm_big<false><<<dim3(CCH / 64, (NB * SCTX + 127) / 128), 256>>>(ctx, ca_v_w, nullptr, nullptr, pCV, NB * SCTX, CCH, DCTX, 0);
    bgemm<true><<<dim3(2, 16, NB * NH), 256>>>(
        pA, pCK, pS, HW, SCTX, DH, CCH, CCH, SCTX,
        (long)HW * CCH, DH, (long)SCTX * CCH, DH, (long)NH * HW * SCTX, (long)HW * SCTX, ISQ);
    softmax_k<<<NB * NH * HW, 128>>>(pS, SCTX);
    bgemm<false><<<dim3(2, 16, NB * NH), 256>>>(
        pS, pCV, pB, HW, DH, SCTX, SCTX, CCH, CCH,
        (long)NH * HW * SCTX, (long)HW * SCTX, (long)SCTX * CCH, DH, (long)HW * CCH, DH, 1.0f);
    gemm_big<false><<<dim3(CCH / 64, NTOK / 128), 256>>>(pB, ca_out_w, ca_out_b, pX, pX, NTOK, CCH, CCH, 0);

    // 5) GeGLU FFN
    layernorm_k<<<NTOK, 256>>>(pX, ln3_s, ln3_b, pB);
    gemm_big<false><<<dim3(FF / 64, NTOK / 128), 256>>>(pB, lin1_w, lin1_b, nullptr, pA, NTOK, FF, CCH, 0);
    geglu_k<<<(int)(((long)NTOK * FFH + 255) / 256), 256>>>(pA, pB);
    gemm_big<false><<<dim3(CCH / 64, NTOK / 128), 256>>>(pB, lin2_w, lin2_b, pX, pX, NTOK, CCH, FFH, 0);

    // 6) final conv + long residual, written as [n, c, h, w]
    gemm_big<true><<<dim3(CCH / 64, NTOK / 128), 256>>>(pX, co_w, co_b, x, out, NTOK, CCH, CCH, 1);
}

// round 7
// speedup vs baseline: 1.5859x; 1.5859x over previous
#include <cuda_runtime.h>
#include <cuda_bf16.h>
#include <math.h>
#include <stdint.h>

#define NB 8
#define CCH 640
#define HW 1024
#define NTOK 8192
#define NH 8
#define DH 80
#define SCTX 77
#define DCTX 512
#define FF 5120
#define FFH 2560
#define GRP 32
#define CPG 20
typedef __nv_bfloat16 bf16;

// ---------------- scratch ----------------
__device__ float g_X[(long)NTOK*CCH];
__device__ float g_F[(long)NTOK*FF];
__device__ float g_S[(long)64*1024*1024];
__device__ float g_CV[8*SCTX*CCH];
__device__ float g_GS[NB*GRP*2];
__device__ bf16 g_t1h[(long)NTOK*CCH], g_t1l[(long)NTOK*CCH];
__device__ bf16 g_t2h[(long)NTOK*FFH], g_t2l[(long)NTOK*FFH];
__device__ bf16 g_q2h[(long)NTOK*1920], g_q2l[(long)NTOK*1920];
__device__ bf16 g_Ph[(long)64*1024*1024], g_Pl[(long)64*1024*1024];
__device__ bf16 g_vth[(long)64*80*1024], g_vtl[(long)64*80*1024];
__device__ bf16 g_vt2h[64*80*80], g_vt2l[64*80*80];
__device__ bf16 g_ckh[8*SCTX*CCH], g_ckl[8*SCTX*CCH];
__device__ bf16 g_cxh[8*SCTX*DCTX], g_cxl[8*SCTX*DCTX];
__device__ bf16 g_wh[8847360], g_wl[8847360];

__device__ __forceinline__ void wr_hl(bf16* h, bf16* l, long i, float v) {
    bf16 hh = __float2bfloat16(v);
    h[i] = hh; l[i] = __float2bfloat16(v - __bfloat162float(hh));
}

// ---------------- small kernels ----------------
__global__ void gn_stats_k(const float* __restrict__ x, float* __restrict__ st) {
    int n = blockIdx.x >> 5, g = blockIdx.x & 31;
    const float* base = x + ((long)n * CCH + g * CPG) * HW;
    const int CNT = CPG * HW;
    float s = 0.f, s2 = 0.f;
    for (int i = threadIdx.x; i < CNT; i += 256) { float v = base[i]; s += v; s2 += v * v; }
    __shared__ float r1[256], r2[256];
    r1[threadIdx.x] = s; r2[threadIdx.x] = s2; __syncthreads();
    for (int t = 128; t > 0; t >>= 1) {
        if (threadIdx.x < t) { r1[threadIdx.x] += r1[threadIdx.x + t]; r2[threadIdx.x] += r2[threadIdx.x + t]; }
        __syncthreads();
    }
    if (threadIdx.x == 0) {
        float mu = r1[0] / CNT, var = r2[0] / CNT - mu * mu;
        st[blockIdx.x * 2] = mu; st[blockIdx.x * 2 + 1] = rsqrtf(var + 1e-6f);
    }
}
__global__ void gn_apply_hl(const float* __restrict__ x, const float* __restrict__ st,
                            const float* __restrict__ gs, const float* __restrict__ gb,
                            bf16* __restrict__ oh, bf16* __restrict__ ol) {
    __shared__ float tile[32][33];
    int n = blockIdx.z, c0 = blockIdx.y * 32, hw0 = blockIdx.x * 32;
    int tx = threadIdx.x, ty = threadIdx.y;
#pragma unroll
    for (int j = 0; j < 4; j++) {
        int c = c0 + ty + j * 8;
        float v = x[((long)n * CCH + c) * HW + hw0 + tx];
        int g = c / CPG;
        tile[ty + j * 8][tx] = (v - st[(n * GRP + g) * 2]) * st[(n * GRP + g) * 2 + 1] * gs[c] + gb[c];
    }
    __syncthreads();
#pragma unroll
    for (int j = 0; j < 4; j++) {
        int hw = hw0 + ty + j * 8;
        wr_hl(oh, ol, ((long)n * HW + hw) * CCH + c0 + tx, tile[tx][ty + j * 8]);
    }
}
__global__ void layernorm_hl(const float* __restrict__ X, const float* __restrict__ s,
                             const float* __restrict__ b, bf16* __restrict__ oh, bf16* __restrict__ ol) {
    long row = blockIdx.x;
    const float* p = X + row * CCH;
    int tid = threadIdx.x;
    float v[3]; int c = 0; float sm = 0.f, s2 = 0.f;
    for (int i = tid; i < CCH; i += 256) { float t = p[i]; v[c++] = t; sm += t; s2 += t * t; }
    __shared__ float r1[256], r2[256];
    r1[tid] = sm; r2[tid] = s2; __syncthreads();
    for (int t = 128; t > 0; t >>= 1) {
        if (tid < t) { r1[tid] += r1[tid + t]; r2[tid] += r2[tid + t]; }
        __syncthreads();
    }
    float mu = r1[0] / CCH, rstd = rsqrtf(r2[0] / CCH - mu * mu + 1e-5f);
    c = 0;
    for (int i = tid; i < CCH; i += 256)
        wr_hl(oh, ol, row * CCH + i, (v[c++] - mu) * rstd * s[i] + b[i]);
}
__global__ void cvt_hl(const float* __restrict__ x, bf16* __restrict__ h, bf16* __restrict__ l, long n) {
    long i = (long)blockIdx.x * 256 + threadIdx.x;
    if (i < n) wr_hl(h, l, i, x[i]);
}
__global__ void wcvtT(const float* __restrict__ w, bf16* __restrict__ oh, bf16* __restrict__ ol, int K, int N) {
    __shared__ float t[32][33];
    int n0 = blockIdx.x * 32, k0 = blockIdx.y * 32;
    int tx = threadIdx.x, ty = threadIdx.y;
#pragma unroll
    for (int j = 0; j < 4; j++) {
        int k = k0 + ty + j * 8;
        t[ty + j * 8][tx] = (k < K && n0 + tx < N) ? w[(long)k * N + n0 + tx] : 0.f;
    }
    __syncthreads();
#pragma unroll
    for (int j = 0; j < 4; j++) {
        int n = n0 + ty + j * 8, k = k0 + tx;
        if (n < N && k < K) wr_hl(oh, ol, (long)n * K + k, t[tx][ty + j * 8]);
    }
}
__global__ void vt_sa(const float* __restrict__ F, bf16* __restrict__ oh, bf16* __restrict__ ol) {
    long i = (long)blockIdx.x * 256 + threadIdx.x;          // [z,d,t]
    if (i >= (long)64 * 80 * 1024) return;
    int t = (int)(i & 1023); long zd = i >> 10;
    int d = (int)(zd % 80); int z = (int)(zd / 80);
    int b = z >> 3, h = z & 7;
    wr_hl(oh, ol, i, F[((long)(b * 1024 + t)) * 1920 + 1280 + h * 80 + d]);
}
__global__ void vt_ca(const float* __restrict__ CV, bf16* __restrict__ oh, bf16* __restrict__ ol) {
    int i = blockIdx.x * 256 + threadIdx.x;                  // [z,d,s]
    if (i >= 64 * 80 * 80) return;
    int s = i % 80; int zd = i / 80;
    int d = zd % 80, z = zd / 80;
    int b = z >> 3, h = z & 7;
    float v = (s < SCTX) ? CV[((long)(b * SCTX + s)) * CCH + h * 80 + d] : 0.f;
    wr_hl(oh, ol, i, v);
}
__global__ void softmax_hl(const float* __restrict__ S, bf16* __restrict__ Ph, bf16* __restrict__ Pl,
                           int Ls, int Lp) {
    __shared__ float red[128];
    long row = blockIdx.x;
    const float* p = S + row * (long)Ls;
    int tid = threadIdx.x;
    float v[8]; int c = 0; float mx = -1e30f;
    for (int i = tid; i < Ls; i += 128) { float t = p[i]; v[c++] = t; mx = fmaxf(mx, t); }
    red[tid] = mx; __syncthreads();
    for (int s = 64; s > 0; s >>= 1) { if (tid < s) red[tid] = fmaxf(red[tid], red[tid + s]); __syncthreads(); }
    mx = red[0]; __syncthreads();
    float sum = 0.f;
    for (int k = 0; k < c; k++) { v[k] = expf(v[k] - mx); sum += v[k]; }
    red[tid] = sum; __syncthreads();
    for (int s = 64; s > 0; s >>= 1) { if (tid < s) red[tid] += red[tid + s]; __syncthreads(); }
    float inv = 1.f / red[0];
    c = 0;
    for (int i = tid; i < Lp; i += 128)
        wr_hl(Ph, Pl, row * (long)Lp + i, (i < Ls) ? v[c++] * inv : 0.f);
}
__global__ void geglu_hl(const float* __restrict__ F, bf16* __restrict__ oh, bf16* __restrict__ ol) {
    long i = (long)blockIdx.x * 256 + threadIdx.x;
    if (i >= (long)NTOK * FFH) return;
    long row = i / FFH; int col = (int)(i % FFH);
    float a = F[row * FF + col], g = F[row * FF + FFH + col];
    wr_hl(oh, ol, i, a * (0.5f * g * (1.0f + erff(g * 0.70710678118654752f))));
}

// ---------------- bf16x3 GEMM via mma.sync (HMMA) ----------------
struct GP {
    const bf16 *Ah, *Al, *Bh, *Bl;
    float* C; const float *bias, *res;
    bf16 *Ch, *Cl;
    int M, N, K, lda, ldb, ldc, nh, permute;
    long aZb, aZh, bZb, bZh, cZb, cZh;
    float alpha;
};

#define LDSROW 80          // bytes per smem row (40 bf16: 32 data + 8 pad)
#define MATB   10240       // bytes per matrix tile (128 * 80)
#define STAGEB 40960       // 4 matrices per stage
#define GEMM_SMEM 81920    // 2 stages

#define LDM4(r, a) asm volatile("ldmatrix.sync.aligned.m8n8.x4.shared.b16 {%0,%1,%2,%3}, [%4];" \
    : "=r"((r)[0]), "=r"((r)[1]), "=r"((r)[2]), "=r"((r)[3]) : "r"(a))

__device__ __forceinline__ void mma_bf16(float* d, const uint32_t* a, const uint32_t* b) {
    asm volatile("mma.sync.aligned.m16n8k16.row.col.f32.bf16.bf16.f32 "
        "{%0,%1,%2,%3}, {%4,%5,%6,%7}, {%8,%9}, {%0,%1,%2,%3};"
        : "+f"(d[0]), "+f"(d[1]), "+f"(d[2]), "+f"(d[3])
        : "r"(a[0]), "r"(a[1]), "r"(a[2]), "r"(a[3]), "r"(b[0]), "r"(b[1]));
}

__global__ __launch_bounds__(256, 1) void mma_gemm(GP p) {
    extern __shared__ char smem[];
    uint32_t sbase = (uint32_t)__cvta_generic_to_shared(smem);
    int tid = threadIdx.x, lane = tid & 31, wid = tid >> 5;
    int wm = wid & 1, wn = wid >> 1;   // 2 x 4 warp grid; warp tile 64x32
    int z = blockIdx.z, b = z / p.nh, h = z - b * p.nh;
    const bf16* Ah = p.Ah + (long)b * p.aZb + (long)h * p.aZh;
    const bf16* Al = p.Al + (long)b * p.aZb + (long)h * p.aZh;
    const bf16* Bh = p.Bh + (long)b * p.bZb + (long)h * p.bZh;
    const bf16* Bl = p.Bl + (long)b * p.bZb + (long)h * p.bZh;
    long coff = (long)b * p.cZb + (long)h * p.cZh;
    int m0 = blockIdx.y * 128, n0 = blockIdx.x * 128;
    int rowsA = p.M - m0; if (rowsA > 128) rowsA = 128;
    int rowsB = p.N - n0; if (rowsB > 128) rowsB = 128;

    float acc[4][4][4] = {};
    int nkb = (p.K + 31) >> 5;

    // ---- stage loader: 4 matrices x 128 rows x 4 chunks(16B) ----
    auto load_stage = [&](int kb, int s) {
        int k0 = kb << 5;
#pragma unroll
        for (int mat = 0; mat < 4; mat++) {
            const bf16* src; int ld, rl;
            if (mat == 0)      { src = Ah + (long)m0 * p.lda; ld = p.lda; rl = rowsA; }
            else if (mat == 1) { src = Al + (long)m0 * p.lda; ld = p.lda; rl = rowsA; }
            else if (mat == 2) { src = Bh + (long)n0 * p.ldb; ld = p.ldb; rl = rowsB; }
            else               { src = Bl + (long)n0 * p.ldb; ld = p.ldb; rl = rowsB; }
            uint32_t dstb = sbase + s * STAGEB + mat * MATB;
#pragma unroll
            for (int i = 0; i < 2; i++) {
                int chunk = tid + (i << 8);
                int r = chunk >> 2, c16 = chunk & 3;
                int kc = k0 + c16 * 8;
                int vsz = (r < rl && kc < p.K) ? 16 : 0;
                int rc = (r < rl) ? r : 0;
                int kcc = (kc < p.K) ? kc : 0;
                uint32_t dst = dstb + r * LDSROW + c16 * 16;
                const bf16* sp = src + (long)rc * ld + kcc;
                asm volatile("cp.async.cg.shared.global [%0], [%1], 16, %2;"
                             :: "r"(dst), "l"(sp), "r"(vsz));
            }
        }
        asm volatile("cp.async.commit_group;");
    };

    load_stage(0, 0);
    for (int kb = 0; kb < nkb; kb++) {
        int s = kb & 1;
        if (kb + 1 < nkb) {
            load_stage(kb + 1, (kb + 1) & 1);
            asm volatile("cp.async.wait_group 1;");
        } else {
            asm volatile("cp.async.wait_group 0;");
        }
        __syncthreads();
        uint32_t stb = sbase + s * STAGEB;
#pragma unroll
        for (int kh = 0; kh < 2; kh++) {
            int k16 = kh * 16;
            uint32_t ah[4][4], al[4][4], bh[4][2], bl[4][2];
            {
                int arow = wm * 64 + (lane & 15);
                int acol = k16 + (lane >> 4) * 8;
#pragma unroll
                for (int mi = 0; mi < 4; mi++) {
                    uint32_t ad = stb + (arow + mi * 16) * LDSROW + acol * 2;
                    LDM4(ah[mi], ad);
                    LDM4(al[mi], ad + MATB);
                }
            }
            {
                int brow = wn * 32 + (lane & 7) + ((lane >> 4) << 3);
                int bcol = k16 + ((lane >> 3) & 1) * 8;
#pragma unroll
                for (int njp = 0; njp < 2; njp++) {
                    uint32_t bd = stb + 2 * MATB + (brow + njp * 16) * LDSROW + bcol * 2;
                    uint32_t r[4];
                    LDM4(r, bd);
                    bh[2*njp][0] = r[0]; bh[2*njp][1] = r[1];
                    bh[2*njp+1][0] = r[2]; bh[2*njp+1][1] = r[3];
                    LDM4(r, bd + MATB);
                    bl[2*njp][0] = r[0]; bl[2*njp][1] = r[1];
                    bl[2*njp+1][0] = r[2]; bl[2*njp+1][1] = r[3];
                }
            }
#pragma unroll
            for (int mi = 0; mi < 4; mi++)
#pragma unroll
                for (int nj = 0; nj < 4; nj++) {
                    mma_bf16(acc[mi][nj], ah[mi], bh[nj]);
                    mma_bf16(acc[mi][nj], ah[mi], bl[nj]);
                    mma_bf16(acc[mi][nj], al[mi], bh[nj]);
                }
        }
        __syncthreads();
    }

    // ---- epilogue ----
    int trow = lane >> 2, tcol = (lane & 3) * 2;
#pragma unroll
    for (int mi = 0; mi < 4; mi++) {
#pragma unroll
        for (int nj = 0; nj < 4; nj++) {
#pragma unroll
            for (int e = 0; e < 4; e++) {
                int gm = m0 + wm * 64 + mi * 16 + trow + ((e >> 1) << 3);
                int gn = n0 + wn * 32 + nj * 8 + tcol + (e & 1);
                if (gm >= p.M || gn >= p.N) continue;
                float v = p.alpha * acc[mi][nj][e];
                if (p.bias) v += __ldg(p.bias + gn);
                long idx;
                if (p.permute) idx = ((long)(gm >> 10) * CCH + gn) * HW + (gm & 1023);
                else idx = coff + (long)gm * p.ldc + gn;
                if (p.res) v += p.res[idx];
                if (p.C) p.C[idx] = v;
                if (p.Ch) wr_hl(p.Ch, p.Cl, idx, v);
            }
        }
    }
}

// ---------------- host ----------------
static inline GP mkgp() { GP p; p.Ah=p.Al=p.Bh=p.Bl=nullptr; p.C=nullptr; p.bias=nullptr; p.res=nullptr;
    p.Ch=p.Cl=nullptr; p.M=p.N=p.K=p.lda=p.ldb=p.ldc=0; p.nh=1; p.permute=0;
    p.aZb=p.aZh=p.bZb=p.bZh=p.cZb=p.cZh=0; p.alpha=1.f; return p; }
static inline void runG(const GP& p, int nz) {
    dim3 g((p.N + 127) / 128, (p.M + 127) / 128, nz);
    mma_gemm<<<g, 256, GEMM_SMEM>>>(p);
}

extern "C" void kernel_launch(void* const* d_in, const int* in_sizes, int n_in,
                              void* d_out, int out_size) {
    const float* x = (const float*)d_in[0];   const float* ctx = (const float*)d_in[1];
    const float* gn_s = (const float*)d_in[2];const float* gn_b = (const float*)d_in[3];
    const float* conv1_w=(const float*)d_in[4];const float* conv1_b=(const float*)d_in[5];
    const float* ln1_s=(const float*)d_in[6]; const float* ln1_b=(const float*)d_in[7];
    const float* sa_in_w=(const float*)d_in[8];const float* sa_out_w=(const float*)d_in[9];
    const float* sa_out_b=(const float*)d_in[10];
    const float* ln2_s=(const float*)d_in[11];const float* ln2_b=(const float*)d_in[12];
    const float* ca_q_w=(const float*)d_in[13];const float* ca_k_w=(const float*)d_in[14];
    const float* ca_v_w=(const float*)d_in[15];const float* ca_out_w=(const float*)d_in[16];
    const float* ca_out_b=(const float*)d_in[17];
    const float* ln3_s=(const float*)d_in[18];const float* ln3_b=(const float*)d_in[19];
    const float* lin1_w=(const float*)d_in[20];const float* lin1_b=(const float*)d_in[21];
    const float* lin2_w=(const float*)d_in[22];const float* lin2_b=(const float*)d_in[23];
    const float* co_w=(const float*)d_in[24]; const float* co_b=(const float*)d_in[25];
    float* out = (float*)d_out;

    cudaFuncSetAttribute(mma_gemm, cudaFuncAttributeMaxDynamicSharedMemorySize, GEMM_SMEM);

    float *pX,*pF,*pS,*pCV,*pGS;
    bf16 *t1h,*t1l,*t2h,*t2l,*q2h,*q2l,*Ph,*Pl,*vth,*vtl,*v2h,*v2l,*ckh,*ckl,*cxh,*cxl,*wh,*wl;
    cudaGetSymbolAddress((void**)&pX,g_X);  cudaGetSymbolAddress((void**)&pF,g_F);
    cudaGetSymbolAddress((void**)&pS,g_S);  cudaGetSymbolAddress((void**)&pCV,g_CV);
    cudaGetSymbolAddress((void**)&pGS,g_GS);
    cudaGetSymbolAddress((void**)&t1h,g_t1h); cudaGetSymbolAddress((void**)&t1l,g_t1l);
    cudaGetSymbolAddress((void**)&t2h,g_t2h); cudaGetSymbolAddress((void**)&t2l,g_t2l);
    cudaGetSymbolAddress((void**)&q2h,g_q2h); cudaGetSymbolAddress((void**)&q2l,g_q2l);
    cudaGetSymbolAddress((void**)&Ph,g_Ph);   cudaGetSymbolAddress((void**)&Pl,g_Pl);
    cudaGetSymbolAddress((void**)&vth,g_vth); cudaGetSymbolAddress((void**)&vtl,g_vtl);
    cudaGetSymbolAddress((void**)&v2h,g_vt2h);cudaGetSymbolAddress((void**)&v2l,g_vt2l);
    cudaGetSymbolAddress((void**)&ckh,g_ckh); cudaGetSymbolAddress((void**)&ckl,g_ckl);
    cudaGetSymbolAddress((void**)&cxh,g_cxh); cudaGetSymbolAddress((void**)&cxl,g_cxl);
    cudaGetSymbolAddress((void**)&wh,g_wh);   cudaGetSymbolAddress((void**)&wl,g_wl);

    const float ISQ = 0.11180339887498949f;
    dim3 tb(32, 8);
    // weight conversions (conv1_w/co_w are [out,in] already = [N,K])
    cvt_hl<<<1600,256>>>(conv1_w, wh+0, wl+0, 409600);
    wcvtT<<<dim3(60,20),tb>>>(sa_in_w,  wh+409600,  wl+409600,  640, 1920);
    wcvtT<<<dim3(20,20),tb>>>(sa_out_w, wh+1638400, wl+1638400, 640, 640);
    wcvtT<<<dim3(20,20),tb>>>(ca_q_w,   wh+2048000, wl+2048000, 640, 640);
    wcvtT<<<dim3(20,16),tb>>>(ca_k_w,   wh+2457600, wl+2457600, 512, 640);
    wcvtT<<<dim3(20,16),tb>>>(ca_v_w,   wh+2785280, wl+2785280, 512, 640);
    wcvtT<<<dim3(20,20),tb>>>(ca_out_w, wh+3112960, wl+3112960, 640, 640);
    wcvtT<<<dim3(160,20),tb>>>(lin1_w,  wh+3522560, wl+3522560, 640, 5120);
    wcvtT<<<dim3(20,80),tb>>>(lin2_w,   wh+6799360, wl+6799360, 2560, 640);
    cvt_hl<<<1600,256>>>(co_w, wh+8437760, wl+8437760, 409600);
    cvt_hl<<<1232,256>>>(ctx, cxh, cxl, 8L*SCTX*DCTX);

    // GN + conv1
    gn_stats_k<<<NB*GRP,256>>>(x, pGS);
    gn_apply_hl<<<dim3(32,20,NB),tb>>>(x, pGS, gn_s, gn_b, t1h, t1l);
    { GP p=mkgp(); p.Ah=t1h;p.Al=t1l;p.lda=640; p.Bh=wh;p.Bl=wl;p.ldb=640;
      p.M=NTOK;p.N=640;p.K=640; p.C=pX;p.ldc=640; p.bias=conv1_b; runG(p,1); }
    // self-attention
    layernorm_hl<<<NTOK,256>>>(pX, ln1_s, ln1_b, t1h, t1l);
    { GP p=mkgp(); p.Ah=t1h;p.Al=t1l;p.lda=640; p.Bh=wh+409600;p.Bl=wl+409600;p.ldb=640;
      p.M=NTOK;p.N=1920;p.K=640; p.C=pF;p.ldc=1920; p.Ch=q2h;p.Cl=q2l; runG(p,1); }
    vt_sa<<<20480,256>>>(pF, vth, vtl);
    { GP p=mkgp(); p.Ah=q2h;p.Al=q2l;p.lda=1920; p.Bh=q2h+640;p.Bl=q2l+640;p.ldb=1920;
      p.M=1024;p.N=1024;p.K=80; p.C=pS;p.ldc=1024; p.nh=NH; p.alpha=ISQ;
      p.aZb=1024L*1920;p.aZh=80; p.bZb=1024L*1920;p.bZh=80; p.cZb=8L*1024*1024;p.cZh=1024L*1024;
      runG(p,64); }
    softmax_hl<<<65536,128>>>(pS, Ph, Pl, 1024, 1024);
    { GP p=mkgp(); p.Ah=Ph;p.Al=Pl;p.lda=1024; p.Bh=vth;p.Bl=vtl;p.ldb=1024;
      p.M=1024;p.N=80;p.K=1024; p.Ch=t2h;p.Cl=t2l;p.ldc=640; p.nh=NH;
      p.aZb=8L*1024*1024;p.aZh=1024L*1024; p.bZb=8L*80*1024;p.bZh=80L*1024;
      p.cZb=1024L*640;p.cZh=80; runG(p,64); }
    { GP p=mkgp(); p.Ah=t2h;p.Al=t2l;p.lda=640; p.Bh=wh+1638400;p.Bl=wl+1638400;p.ldb=640;
      p.M=NTOK;p.N=640;p.K=640; p.C=pX;p.ldc=640; p.bias=sa_out_b; p.res=pX; runG(p,1); }
    // cross-attention
    layernorm_hl<<<NTOK,256>>>(pX, ln2_s, ln2_b, t1h, t1l);
    { GP p=mkgp(); p.Ah=t1h;p.Al=t1l;p.lda=640; p.Bh=wh+2048000;p.Bl=wl+2048000;p.ldb=640;
      p.M=NTOK;p.N=640;p.K=640; p.Ch=q2h;p.Cl=q2l;p.ldc=640; runG(p,1); }
    { GP p=mkgp(); p.Ah=cxh;p.Al=cxl;p.lda=512; p.Bh=wh+2457600;p.Bl=wl+2457600;p.ldb=512;
      p.M=8*SCTX;p.N=640;p.K=512; p.Ch=ckh;p.Cl=ckl;p.ldc=640; runG(p,1); }
    { GP p=mkgp(); p.Ah=cxh;p.Al=cxl;p.lda=512; p.Bh=wh+2785280;p.Bl=wl+2785280;p.ldb=512;
      p.M=8*SCTX;p.N=640;p.K=512; p.C=pCV;p.ldc=640; runG(p,1); }
    vt_ca<<<1600,256>>>(pCV, v2h, v2l);
    { GP p=mkgp(); p.Ah=q2h;p.Al=q2l;p.lda=640; p.Bh=ckh;p.Bl=ckl;p.ldb=640;
      p.M=1024;p.N=SCTX;p.K=80; p.C=pS;p.ldc=SCTX; p.nh=NH; p.alpha=ISQ;
      p.aZb=1024L*640;p.aZh=80; p.bZb=(long)SCTX*640;p.bZh=80;
      p.cZb=8L*1024*SCTX;p.cZh=1024L*SCTX; runG(p,64); }
    softmax_hl<<<65536,128>>>(pS, Ph, Pl, SCTX, 80);
    { GP p=mkgp(); p.Ah=Ph;p.Al=Pl;p.lda=80; p.Bh=v2h;p.Bl=v2l;p.ldb=80;
      p.M=1024;p.N=80;p.K=80; p.Ch=t1h;p.Cl=t1l;p.ldc=640; p.nh=NH;
      p.aZb=8L*1024*80;p.aZh=1024L*80; p.bZb=8L*80*80;p.bZh=80L*80;
      p.cZb=1024L*640;p.cZh=80; runG(p,64); }
    { GP p=mkgp(); p.Ah=t1h;p.Al=t1l;p.lda=640; p.Bh=wh+3112960;p.Bl=wl+3112960;p.ldb=640;
      p.M=NTOK;p.N=640;p.K=640; p.C=pX;p.ldc=640; p.bias=ca_out_b; p.res=pX; runG(p,1); }
    // GeGLU FFN
    layernorm_hl<<<NTOK,256>>>(pX, ln3_s, ln3_b, t1h, t1l);
    { GP p=mkgp(); p.Ah=t1h;p.Al=t1l;p.lda=640; p.Bh=wh+3522560;p.Bl=wl+3522560;p.ldb=640;
      p.M=NTOK;p.N=5120;p.K=640; p.C=pF;p.ldc=5120; p.bias=lin1_b; runG(p,1); }
    geglu_hl<<<81920,256>>>(pF, t2h, t2l);
    { GP p=mkgp(); p.Ah=t2h;p.Al=t2l;p.lda=2560; p.Bh=wh+6799360;p.Bl=wl+6799360;p.ldb=2560;
      p.M=NTOK;p.N=640;p.K=2560; p.C=pX;p.ldc=640; p.bias=lin2_b; p.res=pX;
      p.Ch=t1h;p.Cl=t1l; runG(p,1); }
    // final conv + long residual (permuted NCHW)
    { GP p=mkgp(); p.Ah=t1h;p.Al=t1l;p.lda=640; p.Bh=wh+8437760;p.Bl=wl+8437760;p.ldb=640;
      p.M=NTOK;p.N=640;p.K=640; p.C=out;p.ldc=640; p.bias=co_b; p.res=x; p.permute=1; runG(p,1); }
}

// round 9
// speedup vs baseline: 1.9410x; 1.2239x over previous
#include <cuda_runtime.h>
#include <cuda_bf16.h>
#include <math.h>
#include <stdint.h>

#define NB 8
#define CCH 640
#define HW 1024
#define NTOK 8192
#define NH 8
#define DH 80
#define SCTX 77
#define DCTX 512
#define FF 5120
#define FFH 2560
#define GRP 32
#define CPG 20
typedef __nv_bfloat16 bf16;

// ---------------- scratch ----------------
__device__ float g_X[(long)NTOK*CCH];
__device__ float g_F[(long)NTOK*FF];
__device__ float g_GS[NB*GRP*2];
__device__ bf16 g_t1h[(long)NTOK*CCH], g_t1l[(long)NTOK*CCH];
__device__ bf16 g_t2h[(long)NTOK*FFH], g_t2l[(long)NTOK*FFH];
__device__ bf16 g_q2h[(long)NTOK*1920], g_q2l[(long)NTOK*1920];
__device__ bf16 g_vth[(long)64*80*1024], g_vtl[(long)64*80*1024];
__device__ bf16 g_vt2h[64*80*80], g_vt2l[64*80*80];
__device__ bf16 g_ckh[8*SCTX*CCH], g_ckl[8*SCTX*CCH];
__device__ bf16 g_cvh[8*SCTX*CCH], g_cvl[8*SCTX*CCH];
__device__ bf16 g_cxh[8*SCTX*DCTX], g_cxl[8*SCTX*DCTX];
__device__ bf16 g_wh[8847360], g_wl[8847360];

__device__ __forceinline__ void wr_hl(bf16* h, bf16* l, long i, float v) {
    bf16 hh = __float2bfloat16(v);
    h[i] = hh; l[i] = __float2bfloat16(v - __bfloat162float(hh));
}
__device__ __forceinline__ uint32_t pack_bf2(float a, float b) {
    union { __nv_bfloat162 v; uint32_t u; } c;
    c.v = __halves2bfloat162(__float2bfloat16(a), __float2bfloat16(b));
    return c.u;
}
__device__ __forceinline__ void sts32(uint32_t a, uint32_t v) {
    asm volatile("st.shared.b32 [%0], %1;" :: "r"(a), "r"(v) : "memory");
}

// ---------------- small kernels ----------------
__global__ void gn_stats_k(const float* __restrict__ x, float* __restrict__ st) {
    int n = blockIdx.x >> 5, g = blockIdx.x & 31;
    const float* base = x + ((long)n * CCH + g * CPG) * HW;
    const int CNT = CPG * HW;
    float s = 0.f, s2 = 0.f;
    for (int i = threadIdx.x; i < CNT; i += 256) { float v = base[i]; s += v; s2 += v * v; }
    __shared__ float r1[256], r2[256];
    r1[threadIdx.x] = s; r2[threadIdx.x] = s2; __syncthreads();
    for (int t = 128; t > 0; t >>= 1) {
        if (threadIdx.x < t) { r1[threadIdx.x] += r1[threadIdx.x + t]; r2[threadIdx.x] += r2[threadIdx.x + t]; }
        __syncthreads();
    }
    if (threadIdx.x == 0) {
        float mu = r1[0] / CNT, var = r2[0] / CNT - mu * mu;
        st[blockIdx.x * 2] = mu; st[blockIdx.x * 2 + 1] = rsqrtf(var + 1e-6f);
    }
}
__global__ void gn_apply_hl(const float* __restrict__ x, const float* __restrict__ st,
                            const float* __restrict__ gs, const float* __restrict__ gb,
                            bf16* __restrict__ oh, bf16* __restrict__ ol) {
    __shared__ float tile[32][33];
    int n = blockIdx.z, c0 = blockIdx.y * 32, hw0 = blockIdx.x * 32;
    int tx = threadIdx.x, ty = threadIdx.y;
#pragma unroll
    for (int j = 0; j < 4; j++) {
        int c = c0 + ty + j * 8;
        float v = x[((long)n * CCH + c) * HW + hw0 + tx];
        int g = c / CPG;
        tile[ty + j * 8][tx] = (v - st[(n * GRP + g) * 2]) * st[(n * GRP + g) * 2 + 1] * gs[c] + gb[c];
    }
    __syncthreads();
#pragma unroll
    for (int j = 0; j < 4; j++) {
        int hw = hw0 + ty + j * 8;
        wr_hl(oh, ol, ((long)n * HW + hw) * CCH + c0 + tx, tile[tx][ty + j * 8]);
    }
}
__global__ void layernorm_hl(const float* __restrict__ X, const float* __restrict__ s,
                             const float* __restrict__ b, bf16* __restrict__ oh, bf16* __restrict__ ol) {
    long row = blockIdx.x;
    const float* p = X + row * CCH;
    int tid = threadIdx.x;
    float v[3]; int c = 0; float sm = 0.f, s2 = 0.f;
    for (int i = tid; i < CCH; i += 256) { float t = p[i]; v[c++] = t; sm += t; s2 += t * t; }
    __shared__ float r1[256], r2[256];
    r1[tid] = sm; r2[tid] = s2; __syncthreads();
    for (int t = 128; t > 0; t >>= 1) {
        if (tid < t) { r1[tid] += r1[tid + t]; r2[tid] += r2[tid + t]; }
        __syncthreads();
    }
    float mu = r1[0] / CCH, rstd = rsqrtf(r2[0] / CCH - mu * mu + 1e-5f);
    c = 0;
    for (int i = tid; i < CCH; i += 256)
        wr_hl(oh, ol, row * CCH + i, (v[c++] - mu) * rstd * s[i] + b[i]);
}
__global__ void cvt_hl(const float* __restrict__ x, bf16* __restrict__ h, bf16* __restrict__ l, long n) {
    long i = (long)blockIdx.x * 256 + threadIdx.x;
    if (i < n) wr_hl(h, l, i, x[i]);
}
__global__ void wcvtT(const float* __restrict__ w, bf16* __restrict__ oh, bf16* __restrict__ ol, int K, int N) {
    __shared__ float t[32][33];
    int n0 = blockIdx.x * 32, k0 = blockIdx.y * 32;
    int tx = threadIdx.x, ty = threadIdx.y;
#pragma unroll
    for (int j = 0; j < 4; j++) {
        int k = k0 + ty + j * 8;
        t[ty + j * 8][tx] = (k < K && n0 + tx < N) ? w[(long)k * N + n0 + tx] : 0.f;
    }
    __syncthreads();
#pragma unroll
    for (int j = 0; j < 4; j++) {
        int n = n0 + ty + j * 8, k = k0 + tx;
        if (n < N && k < K) wr_hl(oh, ol, (long)n * K + k, t[tx][ty + j * 8]);
    }
}
// gather V^T (hi/lo) for self-attention from qkv bf16 outputs
__global__ void vt_sa(const bf16* __restrict__ qh, const bf16* __restrict__ ql,
                      bf16* __restrict__ oh, bf16* __restrict__ ol) {
    long i = (long)blockIdx.x * 256 + threadIdx.x;          // [z,d,t]
    if (i >= (long)64 * 80 * 1024) return;
    int t = (int)(i & 1023); long zd = i >> 10;
    int d = (int)(zd % 80); int z = (int)(zd / 80);
    int b = z >> 3, h = z & 7;
    long src = ((long)(b * 1024 + t)) * 1920 + 1280 + h * 80 + d;
    oh[i] = qh[src]; ol[i] = ql[src];
}
// gather V^T (hi/lo) for cross-attention, zero-padded to 80 keys
__global__ void vt_ca(const bf16* __restrict__ cvh, const bf16* __restrict__ cvl,
                      bf16* __restrict__ oh, bf16* __restrict__ ol) {
    int i = blockIdx.x * 256 + threadIdx.x;                  // [z,d,s]
    if (i >= 64 * 80 * 80) return;
    int s = i % 80; int zd = i / 80;
    int d = zd % 80, z = zd / 80;
    int b = z >> 3, h = z & 7;
    if (s < SCTX) {
        long src = ((long)(b * SCTX + s)) * 640 + h * 80 + d;
        oh[i] = cvh[src]; ol[i] = cvl[src];
    } else {
        oh[i] = __float2bfloat16(0.f); ol[i] = __float2bfloat16(0.f);
    }
}
__global__ void geglu_hl(const float* __restrict__ F, bf16* __restrict__ oh, bf16* __restrict__ ol) {
    long i = (long)blockIdx.x * 256 + threadIdx.x;
    if (i >= (long)NTOK * FFH) return;
    long row = i / FFH; int col = (int)(i % FFH);
    float a = F[row * FF + col], g = F[row * FF + FFH + col];
    wr_hl(oh, ol, i, a * (0.5f * g * (1.0f + erff(g * 0.70710678118654752f))));
}

// ---------------- HMMA primitives ----------------
#define LDM4(r, a) asm volatile("ldmatrix.sync.aligned.m8n8.x4.shared.b16 {%0,%1,%2,%3}, [%4];" \
    : "=r"((r)[0]), "=r"((r)[1]), "=r"((r)[2]), "=r"((r)[3]) : "r"(a))

__device__ __forceinline__ void mma_bf16(float* d, const uint32_t* a, const uint32_t* b) {
    asm volatile("mma.sync.aligned.m16n8k16.row.col.f32.bf16.bf16.f32 "
        "{%0,%1,%2,%3}, {%4,%5,%6,%7}, {%8,%9}, {%0,%1,%2,%3};"
        : "+f"(d[0]), "+f"(d[1]), "+f"(d[2]), "+f"(d[3])
        : "r"(a[0]), "r"(a[1]), "r"(a[2]), "r"(a[3]), "r"(b[0]), "r"(b[1]));
}
#define CPA16(dst, src) asm volatile("cp.async.cg.shared.global [%0],[%1],16;" :: "r"(dst), "l"(src))
#define CPA16Z(dst, src, vsz) asm volatile("cp.async.cg.shared.global [%0],[%1],16,%2;" :: "r"(dst), "l"(src), "r"(vsz))
#define CPCOMMIT() asm volatile("cp.async.commit_group;")
#define CPWAIT0()  asm volatile("cp.async.wait_group 0;")

// ---------------- bf16x3 dense GEMM (unchanged from R6) ----------------
struct GP {
    const bf16 *Ah, *Al, *Bh, *Bl;
    float* C; const float *bias, *res;
    bf16 *Ch, *Cl;
    int M, N, K, lda, ldb, ldc, permute;
    float alpha;
};
#define LDSROW 80
#define MATB   10240
#define STAGEB 40960
#define GEMM_SMEM 81920

__global__ __launch_bounds__(256, 1) void mma_gemm(GP p) {
    extern __shared__ char smem[];
    uint32_t sbase = (uint32_t)__cvta_generic_to_shared(smem);
    int tid = threadIdx.x, lane = tid & 31, wid = tid >> 5;
    int wm = wid & 1, wn = wid >> 1;
    const bf16* Ah = p.Ah; const bf16* Al = p.Al;
    const bf16* Bh = p.Bh; const bf16* Bl = p.Bl;
    int m0 = blockIdx.y * 128, n0 = blockIdx.x * 128;
    int rowsA = p.M - m0; if (rowsA > 128) rowsA = 128;
    int rowsB = p.N - n0; if (rowsB > 128) rowsB = 128;

    float acc[4][4][4] = {};
    int nkb = (p.K + 31) >> 5;

    auto load_stage = [&](int kb, int s) {
        int k0 = kb << 5;
#pragma unroll
        for (int mat = 0; mat < 4; mat++) {
            const bf16* src; int ld, rl;
            if (mat == 0)      { src = Ah + (long)m0 * p.lda; ld = p.lda; rl = rowsA; }
            else if (mat == 1) { src = Al + (long)m0 * p.lda; ld = p.lda; rl = rowsA; }
            else if (mat == 2) { src = Bh + (long)n0 * p.ldb; ld = p.ldb; rl = rowsB; }
            else               { src = Bl + (long)n0 * p.ldb; ld = p.ldb; rl = rowsB; }
            uint32_t dstb = sbase + s * STAGEB + mat * MATB;
#pragma unroll
            for (int i = 0; i < 2; i++) {
                int chunk = tid + (i << 8);
                int r = chunk >> 2, c16 = chunk & 3;
                int kc = k0 + c16 * 8;
                int vsz = (r < rl && kc < p.K) ? 16 : 0;
                int rc = (r < rl) ? r : 0;
                int kcc = (kc < p.K) ? kc : 0;
                uint32_t dst = dstb + r * LDSROW + c16 * 16;
                const bf16* sp = src + (long)rc * ld + kcc;
                CPA16Z(dst, sp, vsz);
            }
        }
        CPCOMMIT();
    };

    load_stage(0, 0);
    for (int kb = 0; kb < nkb; kb++) {
        int s = kb & 1;
        if (kb + 1 < nkb) {
            load_stage(kb + 1, (kb + 1) & 1);
            asm volatile("cp.async.wait_group 1;");
        } else {
            CPWAIT0();
        }
        __syncthreads();
        uint32_t stb = sbase + s * STAGEB;
#pragma unroll
        for (int kh = 0; kh < 2; kh++) {
            int k16 = kh * 16;
            uint32_t ah[4][4], al[4][4], bh[4][2], bl[4][2];
            {
                int arow = wm * 64 + (lane & 15);
                int acol = k16 + (lane >> 4) * 8;
#pragma unroll
                for (int mi = 0; mi < 4; mi++) {
                    uint32_t ad = stb + (arow + mi * 16) * LDSROW + acol * 2;
                    LDM4(ah[mi], ad);
                    LDM4(al[mi], ad + MATB);
                }
            }
            {
                int brow = wn * 32 + (lane & 7) + ((lane >> 4) << 3);
                int bcol = k16 + ((lane >> 3) & 1) * 8;
#pragma unroll
                for (int njp = 0; njp < 2; njp++) {
                    uint32_t bd = stb + 2 * MATB + (brow + njp * 16) * LDSROW + bcol * 2;
                    uint32_t r[4];
                    LDM4(r, bd);
                    bh[2*njp][0] = r[0]; bh[2*njp][1] = r[1];
                    bh[2*njp+1][0] = r[2]; bh[2*njp+1][1] = r[3];
                    LDM4(r, bd + MATB);
                    bl[2*njp][0] = r[0]; bl[2*njp][1] = r[1];
                    bl[2*njp+1][0] = r[2]; bl[2*njp+1][1] = r[3];
                }
            }
#pragma unroll
            for (int mi = 0; mi < 4; mi++)
#pragma unroll
                for (int nj = 0; nj < 4; nj++) {
                    mma_bf16(acc[mi][nj], ah[mi], bh[nj]);
                    mma_bf16(acc[mi][nj], ah[mi], bl[nj]);
                    mma_bf16(acc[mi][nj], al[mi], bh[nj]);
                }
        }
        __syncthreads();
    }

    int trow = lane >> 2, tcol = (lane & 3) * 2;
#pragma unroll
    for (int mi = 0; mi < 4; mi++) {
#pragma unroll
        for (int nj = 0; nj < 4; nj++) {
#pragma unroll
            for (int e = 0; e < 4; e++) {
                int gm = m0 + wm * 64 + mi * 16 + trow + ((e >> 1) << 3);
                int gn = n0 + wn * 32 + nj * 8 + tcol + (e & 1);
                if (gm >= p.M || gn >= p.N) continue;
                float v = p.alpha * acc[mi][nj][e];
                if (p.bias) v += __ldg(p.bias + gn);
                long idx;
                if (p.permute) idx = ((long)(gm >> 10) * CCH + gn) * HW + (gm & 1023);
                else idx = (long)gm * p.ldc + gn;
                if (p.res) v += p.res[idx];
                if (p.C) p.C[idx] = v;
                if (p.Ch) wr_hl(p.Ch, p.Cl, idx, v);
            }
        }
    }
}

// ---------------- flash self-attention ----------------
// grid (8 qblocks, 64 z=b*8+h), 256 threads (8 warps x 16 q-rows)
// smem: Qh 0 /Ql 22528 (128x176B); K stage s: 45056+s*22528 (h), +11264 (l), 64x176B
//       V stage s: 90112+s*23040 (h), +11520 (l), 80 rows(d) x 144B (64 keys)
//       Ph 136192 / Pl 154624 (128x144B). total 173056
#define SA_SMEM 173056
#define ISQ 0.11180339887498949f

__global__ __launch_bounds__(256, 1) void flash_sa(
    const bf16* __restrict__ qh, const bf16* __restrict__ ql,
    const bf16* __restrict__ vth, const bf16* __restrict__ vtl,
    bf16* __restrict__ oh, bf16* __restrict__ ol)
{
    extern __shared__ char smem[];
    uint32_t sb = (uint32_t)__cvta_generic_to_shared(smem);
    const uint32_t Qhb = sb, Qlb = sb + 22528;
    int tid = threadIdx.x, lane = tid & 31, w = tid >> 5;
    int z = blockIdx.y, b = z >> 3, h = z & 7;
    int q0 = blockIdx.x * 128;
    const bf16* Qh_src = qh + ((long)(b * 1024 + q0)) * 1920 + h * 80;
    const bf16* Ql_src = ql + ((long)(b * 1024 + q0)) * 1920 + h * 80;
    const bf16* Kh_src = qh + ((long)b * 1024) * 1920 + 640 + h * 80;
    const bf16* Kl_src = ql + ((long)b * 1024) * 1920 + 640 + h * 80;
    const bf16* Vh_src = vth + (long)z * 80 * 1024;
    const bf16* Vl_src = vtl + (long)z * 80 * 1024;

    // Q: 128 rows x 10 chunks, hi+lo
    for (int c = tid; c < 1280; c += 256) {
        int r = c / 10, ch = c - r * 10;
        CPA16(Qhb + r * 176 + ch * 16, Qh_src + (long)r * 1920 + ch * 8);
        CPA16(Qlb + r * 176 + ch * 16, Ql_src + (long)r * 1920 + ch * 8);
    }
    auto load_kv = [&](int kb, int s) {
        uint32_t Kb = sb + 45056 + s * 22528;
        uint32_t Vb = sb + 90112 + s * 23040;
        const bf16* kh = Kh_src + (long)(kb * 64) * 1920;
        const bf16* kl = Kl_src + (long)(kb * 64) * 1920;
        for (int c = tid; c < 640; c += 256) {
            int r = c / 10, ch = c - r * 10;
            CPA16(Kb + r * 176 + ch * 16, kh + (long)r * 1920 + ch * 8);
            CPA16(Kb + 11264 + r * 176 + ch * 16, kl + (long)r * 1920 + ch * 8);
        }
        const bf16* vh = Vh_src + kb * 64;
        const bf16* vl = Vl_src + kb * 64;
        for (int c = tid; c < 640; c += 256) {
            int r = c >> 3, ch = c & 7;
            CPA16(Vb + r * 144 + ch * 16, vh + (long)r * 1024 + ch * 8);
            CPA16(Vb + 11520 + r * 144 + ch * 16, vl + (long)r * 1024 + ch * 8);
        }
    };
    load_kv(0, 0);
    CPCOMMIT();

    float m_[2] = {-1e30f, -1e30f}, l_[2] = {0.f, 0.f};
    float o[10][4] = {};
    int prow = w * 16 + (lane >> 2), pc0 = (lane & 3) * 2;

    for (int kb = 0; kb < 16; kb++) {
        int s = kb & 1;
        CPWAIT0();
        __syncthreads();
        if (kb + 1 < 16) { load_kv(kb + 1, s ^ 1); CPCOMMIT(); }
        uint32_t Kb = sb + 45056 + s * 22528;
        uint32_t Vb = sb + 90112 + s * 23040;
        // ---- S = Q K^T (16 x 64 per warp) ----
        float sacc[8][4] = {};
#pragma unroll
        for (int kk = 0; kk < 5; kk++) {
            uint32_t ah[4], al[4];
            uint32_t aaddr = Qhb + (w * 16 + (lane & 15)) * 176 + (kk * 16 + (lane >> 4) * 8) * 2;
            LDM4(ah, aaddr); LDM4(al, aaddr + 22528);
            uint32_t bh[8][2], bl[8][2];
#pragma unroll
            for (int njp = 0; njp < 4; njp++) {
                uint32_t baddr = Kb + (njp * 16 + (lane & 7) + ((lane >> 4) << 3)) * 176
                               + (kk * 16 + ((lane >> 3) & 1) * 8) * 2;
                uint32_t r[4];
                LDM4(r, baddr);
                bh[2*njp][0] = r[0]; bh[2*njp][1] = r[1];
                bh[2*njp+1][0] = r[2]; bh[2*njp+1][1] = r[3];
                LDM4(r, baddr + 11264);
                bl[2*njp][0] = r[0]; bl[2*njp][1] = r[1];
                bl[2*njp+1][0] = r[2]; bl[2*njp+1][1] = r[3];
            }
#pragma unroll
            for (int nj = 0; nj < 8; nj++) {
                mma_bf16(sacc[nj], ah, bh[nj]);
                mma_bf16(sacc[nj], ah, bl[nj]);
                mma_bf16(sacc[nj], al, bh[nj]);
            }
        }
        // ---- online softmax ----
        float mx0 = -1e30f, mx1 = -1e30f;
#pragma unroll
        for (int nj = 0; nj < 8; nj++) {
            mx0 = fmaxf(mx0, fmaxf(sacc[nj][0], sacc[nj][1]));
            mx1 = fmaxf(mx1, fmaxf(sacc[nj][2], sacc[nj][3]));
        }
        mx0 = fmaxf(mx0, __shfl_xor_sync(0xffffffff, mx0, 1));
        mx0 = fmaxf(mx0, __shfl_xor_sync(0xffffffff, mx0, 2));
        mx1 = fmaxf(mx1, __shfl_xor_sync(0xffffffff, mx1, 1));
        mx1 = fmaxf(mx1, __shfl_xor_sync(0xffffffff, mx1, 2));
        float mn0 = fmaxf(m_[0], mx0 * ISQ), mn1 = fmaxf(m_[1], mx1 * ISQ);
        float sc0 = __expf(m_[0] - mn0), sc1 = __expf(m_[1] - mn1);
        m_[0] = mn0; m_[1] = mn1;
        float rs0 = 0.f, rs1 = 0.f;
#pragma unroll
        for (int nj = 0; nj < 8; nj++) {
            float p0 = __expf(sacc[nj][0] * ISQ - mn0);
            float p1 = __expf(sacc[nj][1] * ISQ - mn0);
            float p2 = __expf(sacc[nj][2] * ISQ - mn1);
            float p3 = __expf(sacc[nj][3] * ISQ - mn1);
            rs0 += p0 + p1; rs1 += p2 + p3;
            // store P hi/lo to smem
            uint32_t a0 = sb + 136192 + prow * 144 + (nj * 8 + pc0) * 2;
            uint32_t a1 = a0 + 8 * 144;
            bf16 h0 = __float2bfloat16(p0), h1 = __float2bfloat16(p1);
            bf16 h2 = __float2bfloat16(p2), h3 = __float2bfloat16(p3);
            union { __nv_bfloat162 v; uint32_t u; } c0, c1, d0, d1;
            c0.v = __halves2bfloat162(h0, h1);
            c1.v = __halves2bfloat162(h2, h3);
            d0.v = __halves2bfloat162(__float2bfloat16(p0 - __bfloat162float(h0)),
                                      __float2bfloat16(p1 - __bfloat162float(h1)));
            d1.v = __halves2bfloat162(__float2bfloat16(p2 - __bfloat162float(h2)),
                                      __float2bfloat16(p3 - __bfloat162float(h3)));
            sts32(a0, c0.u); sts32(a1, c1.u);
            sts32(a0 + 18432, d0.u); sts32(a1 + 18432, d1.u);
        }
        rs0 += __shfl_xor_sync(0xffffffff, rs0, 1);
        rs0 += __shfl_xor_sync(0xffffffff, rs0, 2);
        rs1 += __shfl_xor_sync(0xffffffff, rs1, 1);
        rs1 += __shfl_xor_sync(0xffffffff, rs1, 2);
        l_[0] = l_[0] * sc0 + rs0; l_[1] = l_[1] * sc1 + rs1;
#pragma unroll
        for (int nj = 0; nj < 10; nj++) {
            o[nj][0] *= sc0; o[nj][1] *= sc0; o[nj][2] *= sc1; o[nj][3] *= sc1;
        }
        __syncwarp();
        // ---- O += P V ----
#pragma unroll
        for (int kk = 0; kk < 4; kk++) {
            uint32_t ph4[4], pl4[4];
            uint32_t pa = sb + 136192 + (w * 16 + (lane & 15)) * 144 + (kk * 16 + (lane >> 4) * 8) * 2;
            LDM4(ph4, pa); LDM4(pl4, pa + 18432);
            uint32_t vh2[10][2], vl2[10][2];
#pragma unroll
            for (int njp = 0; njp < 5; njp++) {
                uint32_t va = Vb + (njp * 16 + (lane & 7) + ((lane >> 4) << 3)) * 144
                            + (kk * 16 + ((lane >> 3) & 1) * 8) * 2;
                uint32_t r[4];
                LDM4(r, va);
                vh2[2*njp][0] = r[0]; vh2[2*njp][1] = r[1];
                vh2[2*njp+1][0] = r[2]; vh2[2*njp+1][1] = r[3];
                LDM4(r, va + 11520);
                vl2[2*njp][0] = r[0]; vl2[2*njp][1] = r[1];
                vl2[2*njp+1][0] = r[2]; vl2[2*njp+1][1] = r[3];
            }
#pragma unroll
            for (int nj = 0; nj < 10; nj++) {
                mma_bf16(o[nj], ph4, vh2[nj]);
                mma_bf16(o[nj], ph4, vl2[nj]);
                mma_bf16(o[nj], pl4, vh2[nj]);
            }
        }
        __syncwarp();
    }
    // ---- normalize + store ----
    float inv0 = 1.f / l_[0], inv1 = 1.f / l_[1];
    int trow = lane >> 2, tc = (lane & 3) * 2;
    long tok0 = (long)(b * 1024 + q0 + w * 16 + trow);
#pragma unroll
    for (int nj = 0; nj < 10; nj++) {
        int col = h * 80 + nj * 8 + tc;
        long idx = tok0 * 640 + col;
        float v0 = o[nj][0] * inv0, v1 = o[nj][1] * inv0;
        float v2 = o[nj][2] * inv1, v3 = o[nj][3] * inv1;
        bf16 h0 = __float2bfloat16(v0), h1 = __float2bfloat16(v1);
        bf16 h2 = __float2bfloat16(v2), h3 = __float2bfloat16(v3);
        *(__nv_bfloat162*)(oh + idx) = __halves2bfloat162(h0, h1);
        *(__nv_bfloat162*)(ol + idx) = __halves2bfloat162(
            __float2bfloat16(v0 - __bfloat162float(h0)), __float2bfloat16(v1 - __bfloat162float(h1)));
        long idx2 = idx + 8L * 640;
        *(__nv_bfloat162*)(oh + idx2) = __halves2bfloat162(h2, h3);
        *(__nv_bfloat162*)(ol + idx2) = __halves2bfloat162(
            __float2bfloat16(v2 - __bfloat162float(h2)), __float2bfloat16(v3 - __bfloat162float(h3)));
    }
}

// ---------------- flash cross-attention (77 keys, single block) ----------------
// smem: Qh 0/Ql 22528 (128x176); Kh 45056/Kl 59136 (80x176);
//       Vh 73216/Vl 87296 (80x176); Ph 101376/Pl 123904 (128x176). total 146432
#define CA_SMEM 146432
__global__ __launch_bounds__(256, 1) void flash_ca(
    const bf16* __restrict__ qh, const bf16* __restrict__ ql,
    const bf16* __restrict__ kh, const bf16* __restrict__ kl,
    const bf16* __restrict__ vth, const bf16* __restrict__ vtl,
    bf16* __restrict__ oh, bf16* __restrict__ ol)
{
    extern __shared__ char smem[];
    uint32_t sb = (uint32_t)__cvta_generic_to_shared(smem);
    int tid = threadIdx.x, lane = tid & 31, w = tid >> 5;
    int z = blockIdx.y, b = z >> 3, h = z & 7;
    int q0 = blockIdx.x * 128;
    const bf16* Qh_src = qh + ((long)(b * 1024 + q0)) * 640 + h * 80;
    const bf16* Ql_src = ql + ((long)(b * 1024 + q0)) * 640 + h * 80;
    const bf16* Kh_src = kh + ((long)(b * SCTX)) * 640 + h * 80;
    const bf16* Kl_src = kl + ((long)(b * SCTX)) * 640 + h * 80;
    const bf16* Vh_src = vth + (long)z * 80 * 80;
    const bf16* Vl_src = vtl + (long)z * 80 * 80;

    for (int c = tid; c < 1280; c += 256) {
        int r = c / 10, ch = c - r * 10;
        CPA16(sb + r * 176 + ch * 16, Qh_src + (long)r * 640 + ch * 8);
        CPA16(sb + 22528 + r * 176 + ch * 16, Ql_src + (long)r * 640 + ch * 8);
    }
    for (int c = tid; c < 800; c += 256) {  // K: 80 rows (77 real) x 10
        int r = c / 10, ch = c - r * 10;
        int vsz = (r < SCTX) ? 16 : 0;
        int rc = (r < SCTX) ? r : 0;
        CPA16Z(sb + 45056 + r * 176 + ch * 16, Kh_src + (long)rc * 640 + ch * 8, vsz);
        CPA16Z(sb + 59136 + r * 176 + ch * 16, Kl_src + (long)rc * 640 + ch * 8, vsz);
    }
    for (int c = tid; c < 800; c += 256) {  // V^T: 80 d-rows x 10
        int r = c / 10, ch = c - r * 10;
        CPA16(sb + 73216 + r * 176 + ch * 16, Vh_src + (long)r * 80 + ch * 8);
        CPA16(sb + 87296 + r * 176 + ch * 16, Vl_src + (long)r * 80 + ch * 8);
    }
    CPCOMMIT(); CPWAIT0();
    __syncthreads();

    // S = Q K^T : 16 x 80 per warp
    float sacc[10][4] = {};
#pragma unroll
    for (int kk = 0; kk < 5; kk++) {
        uint32_t ah[4], al[4];
        uint32_t aaddr = sb + (w * 16 + (lane & 15)) * 176 + (kk * 16 + (lane >> 4) * 8) * 2;
        LDM4(ah, aaddr); LDM4(al, aaddr + 22528);
        uint32_t bh[10][2], bl[10][2];
#pragma unroll
        for (int njp = 0; njp < 5; njp++) {
            uint32_t baddr = sb + 45056 + (njp * 16 + (lane & 7) + ((lane >> 4) << 3)) * 176
                           + (kk * 16 + ((lane >> 3) & 1) * 8) * 2;
            uint32_t r[4];
            LDM4(r, baddr);
            bh[2*njp][0] = r[0]; bh[2*njp][1] = r[1];
            bh[2*njp+1][0] = r[2]; bh[2*njp+1][1] = r[3];
            LDM4(r, baddr + 14080);
            bl[2*njp][0] = r[0]; bl[2*njp][1] = r[1];
            bl[2*njp+1][0] = r[2]; bl[2*njp+1][1] = r[3];
        }
#pragma unroll
        for (int nj = 0; nj < 10; nj++) {
            mma_bf16(sacc[nj], ah, bh[nj]);
            mma_bf16(sacc[nj], ah, bl[nj]);
            mma_bf16(sacc[nj], al, bh[nj]);
        }
    }
    // mask cols >= 77
    int pc0 = (lane & 3) * 2;
#pragma unroll
    for (int nj = 0; nj < 10; nj++) {
#pragma unroll
        for (int e = 0; e < 4; e++) {
            int col = nj * 8 + pc0 + (e & 1);
            if (col >= SCTX) sacc[nj][e] = -1e30f;
        }
    }
    // softmax (single pass)
    float mx0 = -1e30f, mx1 = -1e30f;
#pragma unroll
    for (int nj = 0; nj < 10; nj++) {
        mx0 = fmaxf(mx0, fmaxf(sacc[nj][0], sacc[nj][1]));
        mx1 = fmaxf(mx1, fmaxf(sacc[nj][2], sacc[nj][3]));
    }
    mx0 = fmaxf(mx0, __shfl_xor_sync(0xffffffff, mx0, 1));
    mx0 = fmaxf(mx0, __shfl_xor_sync(0xffffffff, mx0, 2));
    mx1 = fmaxf(mx1, __shfl_xor_sync(0xffffffff, mx1, 1));
    mx1 = fmaxf(mx1, __shfl_xor_sync(0xffffffff, mx1, 2));
    mx0 *= ISQ; mx1 *= ISQ;
    float rs0 = 0.f, rs1 = 0.f;
    int prow = w * 16 + (lane >> 2);
#pragma unroll
    for (int nj = 0; nj < 10; nj++) {
        float p0 = __expf(sacc[nj][0] * ISQ - mx0);
        float p1 = __expf(sacc[nj][1] * ISQ - mx0);
        float p2 = __expf(sacc[nj][2] * ISQ - mx1);
        float p3 = __expf(sacc[nj][3] * ISQ - mx1);
        rs0 += p0 + p1; rs1 += p2 + p3;
        uint32_t a0 = sb + 101376 + prow * 176 + (nj * 8 + pc0) * 2;
        uint32_t a1 = a0 + 8 * 176;
        bf16 h0 = __float2bfloat16(p0), h1 = __float2bfloat16(p1);
        bf16 h2 = __float2bfloat16(p2), h3 = __float2bfloat16(p3);
        union { __nv_bfloat162 v; uint32_t u; } c0, c1, d0, d1;
        c0.v = __halves2bfloat162(h0, h1);
        c1.v = __halves2bfloat162(h2, h3);
        d0.v = __halves2bfloat162(__float2bfloat16(p0 - __bfloat162float(h0)),
                                  __float2bfloat16(p1 - __bfloat162float(h1)));
        d1.v = __halves2bfloat162(__float2bfloat16(p2 - __bfloat162float(h2)),
                                  __float2bfloat16(p3 - __bfloat162float(h3)));
        sts32(a0, c0.u); sts32(a1, c1.u);
        sts32(a0 + 22528, d0.u); sts32(a1 + 22528, d1.u);
    }
    rs0 += __shfl_xor_sync(0xffffffff, rs0, 1);
    rs0 += __shfl_xor_sync(0xffffffff, rs0, 2);
    rs1 += __shfl_xor_sync(0xffffffff, rs1, 1);
    rs1 += __shfl_xor_sync(0xffffffff, rs1, 2);
    __syncwarp();
    // O = P V
    float o[10][4] = {};
#pragma unroll
    for (int kk = 0; kk < 5; kk++) {
        uint32_t ph4[4], pl4[4];
        uint32_t pa = sb + 101376 + (w * 16 + (lane & 15)) * 176 + (kk * 16 + (lane >> 4) * 8) * 2;
        LDM4(ph4, pa); LDM4(pl4, pa + 22528);
        uint32_t vh2[10][2], vl2[10][2];
#pragma unroll
        for (int njp = 0; njp < 5; njp++) {
            uint32_t va = sb + 73216 + (njp * 16 + (lane & 7) + ((lane >> 4) << 3)) * 176
                        + (kk * 16 + ((lane >> 3) & 1) * 8) * 2;
            uint32_t r[4];
            LDM4(r, va);
            vh2[2*njp][0] = r[0]; vh2[2*njp][1] = r[1];
            vh2[2*njp+1][0] = r[2]; vh2[2*njp+1][1] = r[3];
            LDM4(r, va + 14080);
            vl2[2*njp][0] = r[0]; vl2[2*njp][1] = r[1];
            vl2[2*njp+1][0] = r[2]; vl2[2*njp+1][1] = r[3];
        }
#pragma unroll
        for (int nj = 0; nj < 10; nj++) {
            mma_bf16(o[nj], ph4, vh2[nj]);
            mma_bf16(o[nj], ph4, vl2[nj]);
            mma_bf16(o[nj], pl4, vh2[nj]);
        }
    }
    float inv0 = 1.f / rs0, inv1 = 1.f / rs1;
    int trow = lane >> 2, tc = (lane & 3) * 2;
    long tok0 = (long)(b * 1024 + q0 + w * 16 + trow);
#pragma unroll
    for (int nj = 0; nj < 10; nj++) {
        int col = h * 80 + nj * 8 + tc;
        long idx = tok0 * 640 + col;
        float v0 = o[nj][0] * inv0, v1 = o[nj][1] * inv0;
        float v2 = o[nj][2] * inv1, v3 = o[nj][3] * inv1;
        bf16 h0 = __float2bfloat16(v0), h1 = __float2bfloat16(v1);
        bf16 h2 = __float2bfloat16(v2), h3 = __float2bfloat16(v3);
        *(__nv_bfloat162*)(oh + idx) = __halves2bfloat162(h0, h1);
        *(__nv_bfloat162*)(ol + idx) = __halves2bfloat162(
            __float2bfloat16(v0 - __bfloat162float(h0)), __float2bfloat16(v1 - __bfloat162float(h1)));
        long idx2 = idx + 8L * 640;
        *(__nv_bfloat162*)(oh + idx2) = __halves2bfloat162(h2, h3);
        *(__nv_bfloat162*)(ol + idx2) = __halves2bfloat162(
            __float2bfloat16(v2 - __bfloat162float(h2)), __float2bfloat16(v3 - __bfloat162float(h3)));
    }
}

// ---------------- host ----------------
static inline GP mkgp() { GP p; p.Ah=p.Al=p.Bh=p.Bl=nullptr; p.C=nullptr; p.bias=nullptr; p.res=nullptr;
    p.Ch=p.Cl=nullptr; p.M=p.N=p.K=p.lda=p.ldb=p.ldc=p.permute=0; p.alpha=1.f; return p; }
static inline void runG(const GP& p) {
    dim3 g((p.N + 127) / 128, (p.M + 127) / 128, 1);
    mma_gemm<<<g, 256, GEMM_SMEM>>>(p);
}

extern "C" void kernel_launch(void* const* d_in, const int* in_sizes, int n_in,
                              void* d_out, int out_size) {
    const float* x = (const float*)d_in[0];   const float* ctx = (const float*)d_in[1];
    const float* gn_s = (const float*)d_in[2];const float* gn_b = (const float*)d_in[3];
    const float* conv1_w=(const float*)d_in[4];const float* conv1_b=(const float*)d_in[5];
    const float* ln1_s=(const float*)d_in[6]; const float* ln1_b=(const float*)d_in[7];
    const float* sa_in_w=(const float*)d_in[8];const float* sa_out_w=(const float*)d_in[9];
    const float* sa_out_b=(const float*)d_in[10];
    const float* ln2_s=(const float*)d_in[11];const float* ln2_b=(const float*)d_in[12];
    const float* ca_q_w=(const float*)d_in[13];const float* ca_k_w=(const float*)d_in[14];
    const float* ca_v_w=(const float*)d_in[15];const float* ca_out_w=(const float*)d_in[16];
    const float* ca_out_b=(const float*)d_in[17];
    const float* ln3_s=(const float*)d_in[18];const float* ln3_b=(const float*)d_in[19];
    const float* lin1_w=(const float*)d_in[20];const float* lin1_b=(const float*)d_in[21];
    const float* lin2_w=(const float*)d_in[22];const float* lin2_b=(const float*)d_in[23];
    const float* co_w=(const float*)d_in[24]; const float* co_b=(const float*)d_in[25];
    float* out = (float*)d_out;

    cudaFuncSetAttribute(mma_gemm, cudaFuncAttributeMaxDynamicSharedMemorySize, GEMM_SMEM);
    cudaFuncSetAttribute(flash_sa, cudaFuncAttributeMaxDynamicSharedMemorySize, SA_SMEM);
    cudaFuncSetAttribute(flash_ca, cudaFuncAttributeMaxDynamicSharedMemorySize, CA_SMEM);

    float *pX,*pF,*pGS;
    bf16 *t1h,*t1l,*t2h,*t2l,*q2h,*q2l,*vth,*vtl,*v2h,*v2l,*ckh,*ckl,*cvh,*cvl,*cxh,*cxl,*wh,*wl;
    cudaGetSymbolAddress((void**)&pX,g_X);  cudaGetSymbolAddress((void**)&pF,g_F);
    cudaGetSymbolAddress((void**)&pGS,g_GS);
    cudaGetSymbolAddress((void**)&t1h,g_t1h); cudaGetSymbolAddress((void**)&t1l,g_t1l);
    cudaGetSymbolAddress((void**)&t2h,g_t2h); cudaGetSymbolAddress((void**)&t2l,g_t2l);
    cudaGetSymbolAddress((void**)&q2h,g_q2h); cudaGetSymbolAddress((void**)&q2l,g_q2l);
    cudaGetSymbolAddress((void**)&vth,g_vth); cudaGetSymbolAddress((void**)&vtl,g_vtl);
    cudaGetSymbolAddress((void**)&v2h,g_vt2h);cudaGetSymbolAddress((void**)&v2l,g_vt2l);
    cudaGetSymbolAddress((void**)&ckh,g_ckh); cudaGetSymbolAddress((void**)&ckl,g_ckl);
    cudaGetSymbolAddress((void**)&cvh,g_cvh); cudaGetSymbolAddress((void**)&cvl,g_cvl);
    cudaGetSymbolAddress((void**)&cxh,g_cxh); cudaGetSymbolAddress((void**)&cxl,g_cxl);
    cudaGetSymbolAddress((void**)&wh,g_wh);   cudaGetSymbolAddress((void**)&wl,g_wl);

    dim3 tb(32, 8);
    // weight conversions (conv1_w/co_w are [out,in] already = [N,K])
    cvt_hl<<<1600,256>>>(conv1_w, wh+0, wl+0, 409600);
    wcvtT<<<dim3(60,20),tb>>>(sa_in_w,  wh+409600,  wl+409600,  640, 1920);
    wcvtT<<<dim3(20,20),tb>>>(sa_out_w, wh+1638400, wl+1638400, 640, 640);
    wcvtT<<<dim3(20,20),tb>>>(ca_q_w,   wh+2048000, wl+2048000, 640, 640);
    wcvtT<<<dim3(20,16),tb>>>(ca_k_w,   wh+2457600, wl+2457600, 512, 640);
    wcvtT<<<dim3(20,16),tb>>>(ca_v_w,   wh+2785280, wl+2785280, 512, 640);
    wcvtT<<<dim3(20,20),tb>>>(ca_out_w, wh+3112960, wl+3112960, 640, 640);
    wcvtT<<<dim3(160,20),tb>>>(lin1_w,  wh+3522560, wl+3522560, 640, 5120);
    wcvtT<<<dim3(20,80),tb>>>(lin2_w,   wh+6799360, wl+6799360, 2560, 640);
    cvt_hl<<<1600,256>>>(co_w, wh+8437760, wl+8437760, 409600);
    cvt_hl<<<1232,256>>>(ctx, cxh, cxl, 8L*SCTX*DCTX);

    // GN + conv1
    gn_stats_k<<<NB*GRP,256>>>(x, pGS);
    gn_apply_hl<<<dim3(32,20,NB),tb>>>(x, pGS, gn_s, gn_b, t1h, t1l);
    { GP p=mkgp(); p.Ah=t1h;p.Al=t1l;p.lda=640; p.Bh=wh;p.Bl=wl;p.ldb=640;
      p.M=NTOK;p.N=640;p.K=640; p.C=pX;p.ldc=640; p.bias=conv1_b; runG(p); }
    // self-attention
    layernorm_hl<<<NTOK,256>>>(pX, ln1_s, ln1_b, t1h, t1l);
    { GP p=mkgp(); p.Ah=t1h;p.Al=t1l;p.lda=640; p.Bh=wh+409600;p.Bl=wl+409600;p.ldb=640;
      p.M=NTOK;p.N=1920;p.K=640; p.Ch=q2h;p.Cl=q2l;p.ldc=1920; runG(p); }
    vt_sa<<<20480,256>>>(q2h, q2l, vth, vtl);
    flash_sa<<<dim3(8,64),256,SA_SMEM>>>(q2h, q2l, vth, vtl, t2h, t2l);
    { GP p=mkgp(); p.Ah=t2h;p.Al=t2l;p.lda=640; p.Bh=wh+1638400;p.Bl=wl+1638400;p.ldb=640;
      p.M=NTOK;p.N=640;p.K=640; p.C=pX;p.ldc=640; p.bias=sa_out_b; p.res=pX; runG(p); }
    // cross-attention
    layernorm_hl<<<NTOK,256>>>(pX, ln2_s, ln2_b, t1h, t1l);
    { GP p=mkgp(); p.Ah=t1h;p.Al=t1l;p.lda=640; p.Bh=wh+2048000;p.Bl=wl+2048000;p.ldb=640;
      p.M=NTOK;p.N=640;p.K=640; p.Ch=q2h;p.Cl=q2l;p.ldc=640; runG(p); }
    { GP p=mkgp(); p.Ah=cxh;p.Al=cxl;p.lda=512; p.Bh=wh+2457600;p.Bl=wl+2457600;p.ldb=512;
      p.M=8*SCTX;p.N=640;p.K=512; p.Ch=ckh;p.Cl=ckl;p.ldc=640; runG(p); }
    { GP p=mkgp(); p.Ah=cxh;p.Al=cxl;p.lda=512; p.Bh=wh+2785280;p.Bl=wl+2785280;p.ldb=512;
      p.M=8*SCTX;p.N=640;p.K=512; p.Ch=cvh;p.Cl=cvl;p.ldc=640; runG(p); }
    vt_ca<<<1600,256>>>(cvh, cvl, v2h, v2l);
    flash_ca<<<dim3(8,64),256,CA_SMEM>>>(q2h, q2l, ckh, ckl, v2h, v2l, t1h, t1l);
    { GP p=mkgp(); p.Ah=t1h;p.Al=t1l;p.lda=640; p.Bh=wh+3112960;p.Bl=wl+3112960;p.ldb=640;
      p.M=NTOK;p.N=640;p.K=640; p.C=pX;p.ldc=640; p.bias=ca_out_b; p.res=pX; runG(p); }
    // GeGLU FFN
    layernorm_hl<<<NTOK,256>>>(pX, ln3_s, ln3_b, t1h, t1l);
    { GP p=mkgp(); p.Ah=t1h;p.Al=t1l;p.lda=640; p.Bh=wh+3522560;p.Bl=wl+3522560;p.ldb=640;
      p.M=NTOK;p.N=5120;p.K=640; p.C=pF;p.ldc=5120; p.bias=lin1_b; runG(p); }
    geglu_hl<<<81920,256>>>(pF, t2h, t2l);
    { GP p=mkgp(); p.Ah=t2h;p.Al=t2l;p.lda=2560; p.Bh=wh+6799360;p.Bl=wl+6799360;p.ldb=2560;
      p.M=NTOK;p.N=640;p.K=2560; p.C=pX;p.ldc=640; p.bias=lin2_b; p.res=pX;
      p.Ch=t1h;p.Cl=t1l; runG(p); }
    // final conv + long residual (permuted NCHW)
    { GP p=mkgp(); p.Ah=t1h;p.Al=t1l;p.lda=640; p.Bh=wh+8437760;p.Bl=wl+8437760;p.ldb=640;
      p.M=NTOK;p.N=640;p.K=640; p.C=out;p.ldc=640; p.bias=co_b; p.res=x; p.permute=1; runG(p); }
}

// round 11
// speedup vs baseline: 2.3863x; 1.2294x over previous
#include <cuda_runtime.h>
#include <cuda_bf16.h>
#include <math.h>
#include <stdint.h>

#define NB 8
#define CCH 640
#define HW 1024
#define NTOK 8192
#define NH 8
#define DH 80
#define SCTX 77
#define DCTX 512
#define FF 5120
#define FFH 2560
#define GRP 32
#define CPG 20
typedef __nv_bfloat16 bf16;

// ---------------- scratch ----------------
__device__ float g_X[(long)NTOK*CCH];
__device__ float g_F[(long)NTOK*FF];
__device__ float g_GS[NB*GRP*2];
__device__ bf16 g_t1h[(long)NTOK*CCH], g_t1l[(long)NTOK*CCH];
__device__ bf16 g_t2h[(long)NTOK*FFH], g_t2l[(long)NTOK*FFH];
__device__ bf16 g_q2h[(long)NTOK*1920], g_q2l[(long)NTOK*1920];
__device__ bf16 g_ckh[8*SCTX*CCH], g_ckl[8*SCTX*CCH];
__device__ bf16 g_cvh[8*SCTX*CCH], g_cvl[8*SCTX*CCH];
__device__ bf16 g_cxh[8*SCTX*DCTX], g_cxl[8*SCTX*DCTX];
__device__ bf16 g_wh[8847360], g_wl[8847360];

__device__ __forceinline__ void wr_hl(bf16* h, bf16* l, long i, float v) {
    bf16 hh = __float2bfloat16(v);
    h[i] = hh; l[i] = __float2bfloat16(v - __bfloat162float(hh));
}
__device__ __forceinline__ void sts32(uint32_t a, uint32_t v) {
    asm volatile("st.shared.b32 [%0], %1;" :: "r"(a), "r"(v) : "memory");
}

// ---------------- small kernels ----------------
__global__ void gn_stats_k(const float* __restrict__ x, float* __restrict__ st) {
    int n = blockIdx.x >> 5, g = blockIdx.x & 31;
    const float* base = x + ((long)n * CCH + g * CPG) * HW;
    const int CNT = CPG * HW;
    float s = 0.f, s2 = 0.f;
    for (int i = threadIdx.x; i < CNT; i += 256) { float v = base[i]; s += v; s2 += v * v; }
    __shared__ float r1[256], r2[256];
    r1[threadIdx.x] = s; r2[threadIdx.x] = s2; __syncthreads();
    for (int t = 128; t > 0; t >>= 1) {
        if (threadIdx.x < t) { r1[threadIdx.x] += r1[threadIdx.x + t]; r2[threadIdx.x] += r2[threadIdx.x + t]; }
        __syncthreads();
    }
    if (threadIdx.x == 0) {
        float mu = r1[0] / CNT, var = r2[0] / CNT - mu * mu;
        st[blockIdx.x * 2] = mu; st[blockIdx.x * 2 + 1] = rsqrtf(var + 1e-6f);
    }
}
__global__ void gn_apply_hl(const float* __restrict__ x, const float* __restrict__ st,
                            const float* __restrict__ gs, const float* __restrict__ gb,
                            bf16* __restrict__ oh, bf16* __restrict__ ol) {
    __shared__ float tile[32][33];
    int n = blockIdx.z, c0 = blockIdx.y * 32, hw0 = blockIdx.x * 32;
    int tx = threadIdx.x, ty = threadIdx.y;
#pragma unroll
    for (int j = 0; j < 4; j++) {
        int c = c0 + ty + j * 8;
        float v = x[((long)n * CCH + c) * HW + hw0 + tx];
        int g = c / CPG;
        tile[ty + j * 8][tx] = (v - st[(n * GRP + g) * 2]) * st[(n * GRP + g) * 2 + 1] * gs[c] + gb[c];
    }
    __syncthreads();
#pragma unroll
    for (int j = 0; j < 4; j++) {
        int hw = hw0 + ty + j * 8;
        wr_hl(oh, ol, ((long)n * HW + hw) * CCH + c0 + tx, tile[tx][ty + j * 8]);
    }
}
__global__ void layernorm_hl(const float* __restrict__ X, const float* __restrict__ s,
                             const float* __restrict__ b, bf16* __restrict__ oh, bf16* __restrict__ ol) {
    long row = blockIdx.x;
    const float* p = X + row * CCH;
    int tid = threadIdx.x;
    float v[3]; int c = 0; float sm = 0.f, s2 = 0.f;
    for (int i = tid; i < CCH; i += 256) { float t = p[i]; v[c++] = t; sm += t; s2 += t * t; }
    __shared__ float r1[256], r2[256];
    r1[tid] = sm; r2[tid] = s2; __syncthreads();
    for (int t = 128; t > 0; t >>= 1) {
        if (tid < t) { r1[tid] += r1[tid + t]; r2[tid] += r2[tid + t]; }
        __syncthreads();
    }
    float mu = r1[0] / CCH, rstd = rsqrtf(r2[0] / CCH - mu * mu + 1e-5f);
    c = 0;
    for (int i = tid; i < CCH; i += 256)
        wr_hl(oh, ol, row * CCH + i, (v[c++] - mu) * rstd * s[i] + b[i]);
}
__global__ void cvt_hl(const float* __restrict__ x, bf16* __restrict__ h, bf16* __restrict__ l, long n) {
    long i = (long)blockIdx.x * 256 + threadIdx.x;
    if (i < n) wr_hl(h, l, i, x[i]);
}
__global__ void wcvtT(const float* __restrict__ w, bf16* __restrict__ oh, bf16* __restrict__ ol, int K, int N) {
    __shared__ float t[32][33];
    int n0 = blockIdx.x * 32, k0 = blockIdx.y * 32;
    int tx = threadIdx.x, ty = threadIdx.y;
#pragma unroll
    for (int j = 0; j < 4; j++) {
        int k = k0 + ty + j * 8;
        t[ty + j * 8][tx] = (k < K && n0 + tx < N) ? w[(long)k * N + n0 + tx] : 0.f;
    }
    __syncthreads();
#pragma unroll
    for (int j = 0; j < 4; j++) {
        int n = n0 + ty + j * 8, k = k0 + tx;
        if (n < N && k < K) wr_hl(oh, ol, (long)n * K + k, t[tx][ty + j * 8]);
    }
}
__global__ void geglu_hl(const float* __restrict__ F, bf16* __restrict__ oh, bf16* __restrict__ ol) {
    long i = (long)blockIdx.x * 256 + threadIdx.x;
    if (i >= (long)NTOK * FFH) return;
    long row = i / FFH; int col = (int)(i % FFH);
    float a = F[row * FF + col], g = F[row * FF + FFH + col];
    wr_hl(oh, ol, i, a * (0.5f * g * (1.0f + erff(g * 0.70710678118654752f))));
}

// ---------------- HMMA primitives ----------------
#define LDM4(r, a) asm volatile("ldmatrix.sync.aligned.m8n8.x4.shared.b16 {%0,%1,%2,%3}, [%4];" \
    : "=r"((r)[0]), "=r"((r)[1]), "=r"((r)[2]), "=r"((r)[3]) : "r"(a))
#define LDM4T(r, a) asm volatile("ldmatrix.sync.aligned.m8n8.x4.trans.shared.b16 {%0,%1,%2,%3}, [%4];" \
    : "=r"((r)[0]), "=r"((r)[1]), "=r"((r)[2]), "=r"((r)[3]) : "r"(a))

__device__ __forceinline__ void mma_bf16(float* d, const uint32_t* a, const uint32_t* b) {
    asm volatile("mma.sync.aligned.m16n8k16.row.col.f32.bf16.bf16.f32 "
        "{%0,%1,%2,%3}, {%4,%5,%6,%7}, {%8,%9}, {%0,%1,%2,%3};"
        : "+f"(d[0]), "+f"(d[1]), "+f"(d[2]), "+f"(d[3])
        : "r"(a[0]), "r"(a[1]), "r"(a[2]), "r"(a[3]), "r"(b[0]), "r"(b[1]));
}
#define CPA16(dst, src) asm volatile("cp.async.cg.shared.global [%0],[%1],16;" :: "r"(dst), "l"(src))
#define CPA16Z(dst, src, vsz) asm volatile("cp.async.cg.shared.global [%0],[%1],16,%2;" :: "r"(dst), "l"(src), "r"(vsz))
#define CPCOMMIT() asm volatile("cp.async.commit_group;")
#define CPWAIT0()  asm volatile("cp.async.wait_group 0;")
#define CPWAIT1()  asm volatile("cp.async.wait_group 1;")

// ---------------- bf16x3 dense GEMM: 128x64 tile, BK=32, 3-stage, occ 2 ----------------
struct GP {
    const bf16 *Ah, *Al, *Bh, *Bl;
    float* C; const float *bias, *res;
    bf16 *Ch, *Cl;
    int M, N, K, lda, ldb, ldc, permute;
    float alpha;
};
#define ARO 80            // smem row bytes (32 bf16 + pad)
#define A_MAT 10240       // 128*80
#define B_MAT 5120        // 64*80
#define BOFF  20480       // B base within stage
#define STG   30720
#define GEMM_SMEM (3*STG) // 92160

__global__ __launch_bounds__(256, 2) void mma_gemm(GP p) {
    extern __shared__ char smem[];
    uint32_t sb = (uint32_t)__cvta_generic_to_shared(smem);
    int tid = threadIdx.x, lane = tid & 31, wid = tid >> 5;
    int wm = wid & 3, wn = wid >> 2;       // 4x2 warp grid; warp tile 32x32
    const bf16 *Ah = p.Ah, *Al = p.Al, *Bh = p.Bh, *Bl = p.Bl;
    int m0 = blockIdx.y * 128, n0 = blockIdx.x * 64;
    int rowsA = p.M - m0; if (rowsA > 128) rowsA = 128;
    int rowsB = p.N - n0; if (rowsB > 64) rowsB = 64;

    float acc[2][4][4] = {};
    int nkb = p.K >> 5;   // all K are multiples of 32

    auto load_stage = [&](int kb, int s) {
        int k0 = kb << 5;
        uint32_t base = sb + (uint32_t)s * STG;
#pragma unroll
        for (int i = 0; i < 6; i++) {
            int c = tid + (i << 8);
            if (c < 1024) {                      // A hi/lo: 2 x 512 chunks
                int mat = c >> 9, cc = c & 511;
                int r = cc >> 2, ch = cc & 3;
                const bf16* src = (mat ? Al : Ah) + (long)(m0 + (r < rowsA ? r : 0)) * p.lda + k0 + ch * 8;
                CPA16Z(base + mat * A_MAT + r * ARO + ch * 16, src, (r < rowsA) ? 16 : 0);
            } else {                              // B hi/lo: 2 x 256 chunks
                int c2 = c - 1024;
                int mat = c2 >> 8, cc = c2 & 255;
                int r = cc >> 2, ch = cc & 3;
                const bf16* src = (mat ? Bl : Bh) + (long)(n0 + (r < rowsB ? r : 0)) * p.ldb + k0 + ch * 8;
                CPA16Z(base + BOFF + mat * B_MAT + r * ARO + ch * 16, src, (r < rowsB) ? 16 : 0);
            }
        }
        CPCOMMIT();
    };

    load_stage(0, 0);
    load_stage(1, 1);
    int slot = 0;
    for (int kb = 0; kb < nkb; kb++) {
        if (kb == nkb - 1) { CPWAIT0(); } else { CPWAIT1(); }
        __syncthreads();
        if (kb + 2 < nkb) {
            int s2 = slot + 2; if (s2 >= 3) s2 -= 3;
            load_stage(kb + 2, s2);
        }
        uint32_t stb = sb + (uint32_t)slot * STG;
#pragma unroll
        for (int kh = 0; kh < 2; kh++) {
            uint32_t ah[2][4], al[2][4], bh[4][2], bl[4][2];
            int arow = wm * 32 + (lane & 15);
            uint32_t aB = (uint32_t)((kh * 16 + (lane >> 4) * 8) * 2);
#pragma unroll
            for (int mi = 0; mi < 2; mi++) {
                uint32_t ad = stb + (arow + mi * 16) * ARO + aB;
                LDM4(ah[mi], ad);
                LDM4(al[mi], ad + A_MAT);
            }
            int brow = wn * 32 + (lane & 7) + ((lane >> 4) << 3);
            uint32_t bB = (uint32_t)((kh * 16 + ((lane >> 3) & 1) * 8) * 2);
#pragma unroll
            for (int njp = 0; njp < 2; njp++) {
                uint32_t bd = stb + BOFF + (brow + njp * 16) * ARO + bB;
                uint32_t r[4];
                LDM4(r, bd);
                bh[2*njp][0] = r[0]; bh[2*njp][1] = r[1];
                bh[2*njp+1][0] = r[2]; bh[2*njp+1][1] = r[3];
                LDM4(r, bd + B_MAT);
                bl[2*njp][0] = r[0]; bl[2*njp][1] = r[1];
                bl[2*njp+1][0] = r[2]; bl[2*njp+1][1] = r[3];
            }
#pragma unroll
            for (int mi = 0; mi < 2; mi++)
#pragma unroll
                for (int nj = 0; nj < 4; nj++) {
                    mma_bf16(acc[mi][nj], ah[mi], bh[nj]);
                    mma_bf16(acc[mi][nj], ah[mi], bl[nj]);
                    mma_bf16(acc[mi][nj], al[mi], bh[nj]);
                }
        }
        if (++slot == 3) slot = 0;
    }

    int trow = lane >> 2, tcol = (lane & 3) * 2;
#pragma unroll
    for (int mi = 0; mi < 2; mi++) {
#pragma unroll
        for (int nj = 0; nj < 4; nj++) {
#pragma unroll
            for (int e = 0; e < 4; e++) {
                int gm = m0 + wm * 32 + mi * 16 + trow + ((e >> 1) << 3);
                int gn = n0 + wn * 32 + nj * 8 + tcol + (e & 1);
                if (gm >= p.M || gn >= p.N) continue;
                float v = p.alpha * acc[mi][nj][e];
                if (p.bias) v += __ldg(p.bias + gn);
                long idx;
                if (p.permute) idx = ((long)(gm >> 10) * CCH + gn) * HW + (gm & 1023);
                else idx = (long)gm * p.ldc + gn;
                if (p.res) v += p.res[idx];
                if (p.C) p.C[idx] = v;
                if (p.Ch) wr_hl(p.Ch, p.Cl, idx, v);
            }
        }
    }
}

// ---------------- flash self-attention ----------------
// grid (8 qblocks, 64 z), 256 threads. V loaded token-major; PV uses ldmatrix.trans.
// smem: Qh 0 / Ql 22528 (128x176B); K stage s: 45056+s*22528 (hi, lo +11264), 64x176B
//       V stage s: 90112+s*22528 (hi, lo +11264), 64 keys x 176B (80 d)
//       Ph 135168 / Pl 153600 (128x144B). total 172032
#define SA_SMEM 172032
#define ISQ 0.11180339887498949f

__global__ __launch_bounds__(256, 1) void flash_sa(
    const bf16* __restrict__ qh, const bf16* __restrict__ ql,
    bf16* __restrict__ oh, bf16* __restrict__ ol)
{
    extern __shared__ char smem[];
    uint32_t sb = (uint32_t)__cvta_generic_to_shared(smem);
    const uint32_t Qhb = sb, Qlb = sb + 22528;
    int tid = threadIdx.x, lane = tid & 31, w = tid >> 5;
    int z = blockIdx.y, b = z >> 3, h = z & 7;
    int q0 = blockIdx.x * 128;
    const bf16* Qh_src = qh + ((long)(b * 1024 + q0)) * 1920 + h * 80;
    const bf16* Ql_src = ql + ((long)(b * 1024 + q0)) * 1920 + h * 80;
    const bf16* Kh_src = qh + ((long)b * 1024) * 1920 + 640 + h * 80;
    const bf16* Kl_src = ql + ((long)b * 1024) * 1920 + 640 + h * 80;
    const bf16* Vh_src = qh + ((long)b * 1024) * 1920 + 1280 + h * 80;
    const bf16* Vl_src = ql + ((long)b * 1024) * 1920 + 1280 + h * 80;

    for (int c = tid; c < 1280; c += 256) {
        int r = c / 10, ch = c - r * 10;
        CPA16(Qhb + r * 176 + ch * 16, Qh_src + (long)r * 1920 + ch * 8);
        CPA16(Qlb + r * 176 + ch * 16, Ql_src + (long)r * 1920 + ch * 8);
    }
    auto load_kv = [&](int kb, int s) {
        uint32_t Kb = sb + 45056 + s * 22528;
        uint32_t Vb = sb + 90112 + s * 22528;
        const bf16* kh = Kh_src + (long)(kb * 64) * 1920;
        const bf16* kl = Kl_src + (long)(kb * 64) * 1920;
        const bf16* vh = Vh_src + (long)(kb * 64) * 1920;
        const bf16* vl = Vl_src + (long)(kb * 64) * 1920;
        for (int c = tid; c < 640; c += 256) {
            int r = c / 10, ch = c - r * 10;
            CPA16(Kb + r * 176 + ch * 16, kh + (long)r * 1920 + ch * 8);
            CPA16(Kb + 11264 + r * 176 + ch * 16, kl + (long)r * 1920 + ch * 8);
            CPA16(Vb + r * 176 + ch * 16, vh + (long)r * 1920 + ch * 8);
            CPA16(Vb + 11264 + r * 176 + ch * 16, vl + (long)r * 1920 + ch * 8);
        }
    };
    load_kv(0, 0);
    CPCOMMIT();

    float m_[2] = {-1e30f, -1e30f}, l_[2] = {0.f, 0.f};
    float o[10][4] = {};
    int prow = w * 16 + (lane >> 2), pc0 = (lane & 3) * 2;

    for (int kb = 0; kb < 16; kb++) {
        int s = kb & 1;
        CPWAIT0();
        __syncthreads();
        if (kb + 1 < 16) { load_kv(kb + 1, s ^ 1); CPCOMMIT(); }
        uint32_t Kb = sb + 45056 + s * 22528;
        uint32_t Vb = sb + 90112 + s * 22528;
        // ---- S = Q K^T ----
        float sacc[8][4] = {};
#pragma unroll
        for (int kk = 0; kk < 5; kk++) {
            uint32_t ah[4], al[4];
            uint32_t aaddr = Qhb + (w * 16 + (lane & 15)) * 176 + (kk * 16 + (lane >> 4) * 8) * 2;
            LDM4(ah, aaddr); LDM4(al, aaddr + 22528);
            uint32_t bh[8][2], bl[8][2];
#pragma unroll
            for (int njp = 0; njp < 4; njp++) {
                uint32_t baddr = Kb + (njp * 16 + (lane & 7) + ((lane >> 4) << 3)) * 176
                               + (kk * 16 + ((lane >> 3) & 1) * 8) * 2;
                uint32_t r[4];
                LDM4(r, baddr);
                bh[2*njp][0] = r[0]; bh[2*njp][1] = r[1];
                bh[2*njp+1][0] = r[2]; bh[2*njp+1][1] = r[3];
                LDM4(r, baddr + 11264);
                bl[2*njp][0] = r[0]; bl[2*njp][1] = r[1];
                bl[2*njp+1][0] = r[2]; bl[2*njp+1][1] = r[3];
            }
#pragma unroll
            for (int nj = 0; nj < 8; nj++) {
                mma_bf16(sacc[nj], ah, bh[nj]);
                mma_bf16(sacc[nj], ah, bl[nj]);
                mma_bf16(sacc[nj], al, bh[nj]);
            }
        }
        // ---- online softmax ----
        float mx0 = -1e30f, mx1 = -1e30f;
#pragma unroll
        for (int nj = 0; nj < 8; nj++) {
            mx0 = fmaxf(mx0, fmaxf(sacc[nj][0], sacc[nj][1]));
            mx1 = fmaxf(mx1, fmaxf(sacc[nj][2], sacc[nj][3]));
        }
        mx0 = fmaxf(mx0, __shfl_xor_sync(0xffffffff, mx0, 1));
        mx0 = fmaxf(mx0, __shfl_xor_sync(0xffffffff, mx0, 2));
        mx1 = fmaxf(mx1, __shfl_xor_sync(0xffffffff, mx1, 1));
        mx1 = fmaxf(mx1, __shfl_xor_sync(0xffffffff, mx1, 2));
        float mn0 = fmaxf(m_[0], mx0 * ISQ), mn1 = fmaxf(m_[1], mx1 * ISQ);
        float sc0 = __expf(m_[0] - mn0), sc1 = __expf(m_[1] - mn1);
        m_[0] = mn0; m_[1] = mn1;
        float rs0 = 0.f, rs1 = 0.f;
#pragma unroll
        for (int nj = 0; nj < 8; nj++) {
            float p0 = __expf(sacc[nj][0] * ISQ - mn0);
            float p1 = __expf(sacc[nj][1] * ISQ - mn0);
            float p2 = __expf(sacc[nj][2] * ISQ - mn1);
            float p3 = __expf(sacc[nj][3] * ISQ - mn1);
            rs0 += p0 + p1; rs1 += p2 + p3;
            uint32_t a0 = sb + 135168 + prow * 144 + (nj * 8 + pc0) * 2;
            uint32_t a1 = a0 + 8 * 144;
            bf16 h0 = __float2bfloat16(p0), h1 = __float2bfloat16(p1);
            bf16 h2 = __float2bfloat16(p2), h3 = __float2bfloat16(p3);
            union { __nv_bfloat162 v; uint32_t u; } c0, c1, d0, d1;
            c0.v = __halves2bfloat162(h0, h1);
            c1.v = __halves2bfloat162(h2, h3);
            d0.v = __halves2bfloat162(__float2bfloat16(p0 - __bfloat162float(h0)),
                                      __float2bfloat16(p1 - __bfloat162float(h1)));
            d1.v = __halves2bfloat162(__float2bfloat16(p2 - __bfloat162float(h2)),
                                      __float2bfloat16(p3 - __bfloat162float(h3)));
            sts32(a0, c0.u); sts32(a1, c1.u);
            sts32(a0 + 18432, d0.u); sts32(a1 + 18432, d1.u);
        }
        rs0 += __shfl_xor_sync(0xffffffff, rs0, 1);
        rs0 += __shfl_xor_sync(0xffffffff, rs0, 2);
        rs1 += __shfl_xor_sync(0xffffffff, rs1, 1);
        rs1 += __shfl_xor_sync(0xffffffff, rs1, 2);
        l_[0] = l_[0] * sc0 + rs0; l_[1] = l_[1] * sc1 + rs1;
#pragma unroll
        for (int nj = 0; nj < 10; nj++) {
            o[nj][0] *= sc0; o[nj][1] *= sc0; o[nj][2] *= sc1; o[nj][3] *= sc1;
        }
        __syncwarp();
        // ---- O += P V  (V token-major, ldmatrix.trans) ----
#pragma unroll
        for (int kk = 0; kk < 4; kk++) {
            uint32_t ph4[4], pl4[4];
            uint32_t pa = sb + 135168 + (w * 16 + (lane & 15)) * 144 + (kk * 16 + (lane >> 4) * 8) * 2;
            LDM4(ph4, pa); LDM4(pl4, pa + 18432);
            uint32_t vh2[10][2], vl2[10][2];
#pragma unroll
            for (int njp = 0; njp < 5; njp++) {
                uint32_t va = Vb + (kk * 16 + (lane & 7) + ((lane >> 3) & 1) * 8) * 176
                            + (njp * 16 + ((lane >> 4) << 3)) * 2;
                uint32_t r[4];
                LDM4T(r, va);
                vh2[2*njp][0] = r[0]; vh2[2*njp][1] = r[1];
                vh2[2*njp+1][0] = r[2]; vh2[2*njp+1][1] = r[3];
                LDM4T(r, va + 11264);
                vl2[2*njp][0] = r[0]; vl2[2*njp][1] = r[1];
                vl2[2*njp+1][0] = r[2]; vl2[2*njp+1][1] = r[3];
            }
#pragma unroll
            for (int nj = 0; nj < 10; nj++) {
                mma_bf16(o[nj], ph4, vh2[nj]);
                mma_bf16(o[nj], ph4, vl2[nj]);
                mma_bf16(o[nj], pl4, vh2[nj]);
            }
        }
        __syncwarp();
    }
    float inv0 = 1.f / l_[0], inv1 = 1.f / l_[1];
    int trow = lane >> 2, tc = (lane & 3) * 2;
    long tok0 = (long)(b * 1024 + q0 + w * 16 + trow);
#pragma unroll
    for (int nj = 0; nj < 10; nj++) {
        int col = h * 80 + nj * 8 + tc;
        long idx = tok0 * 640 + col;
        float v0 = o[nj][0] * inv0, v1 = o[nj][1] * inv0;
        float v2 = o[nj][2] * inv1, v3 = o[nj][3] * inv1;
        bf16 h0 = __float2bfloat16(v0), h1 = __float2bfloat16(v1);
        bf16 h2 = __float2bfloat16(v2), h3 = __float2bfloat16(v3);
        *(__nv_bfloat162*)(oh + idx) = __halves2bfloat162(h0, h1);
        *(__nv_bfloat162*)(ol + idx) = __halves2bfloat162(
            __float2bfloat16(v0 - __bfloat162float(h0)), __float2bfloat16(v1 - __bfloat162float(h1)));
        long idx2 = idx + 8L * 640;
        *(__nv_bfloat162*)(oh + idx2) = __halves2bfloat162(h2, h3);
        *(__nv_bfloat162*)(ol + idx2) = __halves2bfloat162(
            __float2bfloat16(v2 - __bfloat162float(h2)), __float2bfloat16(v3 - __bfloat162float(h3)));
    }
}

// ---------------- flash cross-attention (77 keys) ----------------
// smem: Qh 0/Ql 22528; Kh 45056/Kl 59136 (80x176); Vh 73216/Vl 87296 (80 keys x 176, token-major);
//       Ph 101376/Pl 123904 (128x176). total 146432
#define CA_SMEM 146432
__global__ __launch_bounds__(256, 1) void flash_ca(
    const bf16* __restrict__ qh, const bf16* __restrict__ ql,
    const bf16* __restrict__ kh, const bf16* __restrict__ kl,
    const bf16* __restrict__ vh, const bf16* __restrict__ vl,
    bf16* __restrict__ oh, bf16* __restrict__ ol)
{
    extern __shared__ char smem[];
    uint32_t sb = (uint32_t)__cvta_generic_to_shared(smem);
    int tid = threadIdx.x, lane = tid & 31, w = tid >> 5;
    int z = blockIdx.y, b = z >> 3, h = z & 7;
    int q0 = blockIdx.x * 128;
    const bf16* Qh_src = qh + ((long)(b * 1024 + q0)) * 640 + h * 80;
    const bf16* Ql_src = ql + ((long)(b * 1024 + q0)) * 640 + h * 80;
    const bf16* Kh_src = kh + ((long)(b * SCTX)) * 640 + h * 80;
    const bf16* Kl_src = kl + ((long)(b * SCTX)) * 640 + h * 80;
    const bf16* Vh_src = vh + ((long)(b * SCTX)) * 640 + h * 80;
    const bf16* Vl_src = vl + ((long)(b * SCTX)) * 640 + h * 80;

    for (int c = tid; c < 1280; c += 256) {
        int r = c / 10, ch = c - r * 10;
        CPA16(sb + r * 176 + ch * 16, Qh_src + (long)r * 640 + ch * 8);
        CPA16(sb + 22528 + r * 176 + ch * 16, Ql_src + (long)r * 640 + ch * 8);
    }
    for (int c = tid; c < 800; c += 256) {
        int r = c / 10, ch = c - r * 10;
        int vsz = (r < SCTX) ? 16 : 0;
        int rc = (r < SCTX) ? r : 0;
        CPA16Z(sb + 45056 + r * 176 + ch * 16, Kh_src + (long)rc * 640 + ch * 8, vsz);
        CPA16Z(sb + 59136 + r * 176 + ch * 16, Kl_src + (long)rc * 640 + ch * 8, vsz);
        CPA16Z(sb + 73216 + r * 176 + ch * 16, Vh_src + (long)rc * 640 + ch * 8, vsz);
        CPA16Z(sb + 87296 + r * 176 + ch * 16, Vl_src + (long)rc * 640 + ch * 8, vsz);
    }
    CPCOMMIT(); CPWAIT0();
    __syncthreads();

    float sacc[10][4] = {};
#pragma unroll
    for (int kk = 0; kk < 5; kk++) {
        uint32_t ah[4], al[4];
        uint32_t aaddr = sb + (w * 16 + (lane & 15)) * 176 + (kk * 16 + (lane >> 4) * 8) * 2;
        LDM4(ah, aaddr); LDM4(al, aaddr + 22528);
        uint32_t bh[10][2], bl[10][2];
#pragma unroll
        for (int njp = 0; njp < 5; njp++) {
            uint32_t baddr = sb + 45056 + (njp * 16 + (lane & 7) + ((lane >> 4) << 3)) * 176
                           + (kk * 16 + ((lane >> 3) & 1) * 8) * 2;
            uint32_t r[4];
            LDM4(r, baddr);
            bh[2*njp][0] = r[0]; bh[2*njp][1] = r[1];
            bh[2*njp+1][0] = r[2]; bh[2*njp+1][1] = r[3];
            LDM4(r, baddr + 14080);
            bl[2*njp][0] = r[0]; bl[2*njp][1] = r[1];
            bl[2*njp+1][0] = r[2]; bl[2*njp+1][1] = r[3];
        }
#pragma unroll
        for (int nj = 0; nj < 10; nj++) {
            mma_bf16(sacc[nj], ah, bh[nj]);
            mma_bf16(sacc[nj], ah, bl[nj]);
            mma_bf16(sacc[nj], al, bh[nj]);
        }
    }
    int pc0 = (lane & 3) * 2;
#pragma unroll
    for (int nj = 0; nj < 10; nj++)
#pragma unroll
        for (int e = 0; e < 4; e++) {
            int col = nj * 8 + pc0 + (e & 1);
            if (col >= SCTX) sacc[nj][e] = -1e30f;
        }
    float mx0 = -1e30f, mx1 = -1e30f;
#pragma unroll
    for (int nj = 0; nj < 10; nj++) {
        mx0 = fmaxf(mx0, fmaxf(sacc[nj][0], sacc[nj][1]));
        mx1 = fmaxf(mx1, fmaxf(sacc[nj][2], sacc[nj][3]));
    }
    mx0 = fmaxf(mx0, __shfl_xor_sync(0xffffffff, mx0, 1));
    mx0 = fmaxf(mx0, __shfl_xor_sync(0xffffffff, mx0, 2));
    mx1 = fmaxf(mx1, __shfl_xor_sync(0xffffffff, mx1, 1));
    mx1 = fmaxf(mx1, __shfl_xor_sync(0xffffffff, mx1, 2));
    mx0 *= ISQ; mx1 *= ISQ;
    float rs0 = 0.f, rs1 = 0.f;
    int prow = w * 16 + (lane >> 2);
#pragma unroll
    for (int nj = 0; nj < 10; nj++) {
        float p0 = __expf(sacc[nj][0] * ISQ - mx0);
        float p1 = __expf(sacc[nj][1] * ISQ - mx0);
        float p2 = __expf(sacc[nj][2] * ISQ - mx1);
        float p3 = __expf(sacc[nj][3] * ISQ - mx1);
        rs0 += p0 + p1; rs1 += p2 + p3;
        uint32_t a0 = sb + 101376 + prow * 176 + (nj * 8 + pc0) * 2;
        uint32_t a1 = a0 + 8 * 176;
        bf16 h0 = __float2bfloat16(p0), h1 = __float2bfloat16(p1);
        bf16 h2 = __float2bfloat16(p2), h3 = __float2bfloat16(p3);
        union { __nv_bfloat162 v; uint32_t u; } c0, c1, d0, d1;
        c0.v = __halves2bfloat162(h0, h1);
        c1.v = __halves2bfloat162(h2, h3);
        d0.v = __halves2bfloat162(__float2bfloat16(p0 - __bfloat162float(h0)),
                                  __float2bfloat16(p1 - __bfloat162float(h1)));
        d1.v = __halves2bfloat162(__float2bfloat16(p2 - __bfloat162float(h2)),
                                  __float2bfloat16(p3 - __bfloat162float(h3)));
        sts32(a0, c0.u); sts32(a1, c1.u);
        sts32(a0 + 22528, d0.u); sts32(a1 + 22528, d1.u);
    }
    rs0 += __shfl_xor_sync(0xffffffff, rs0, 1);
    rs0 += __shfl_xor_sync(0xffffffff, rs0, 2);
    rs1 += __shfl_xor_sync(0xffffffff, rs1, 1);
    rs1 += __shfl_xor_sync(0xffffffff, rs1, 2);
    __syncwarp();
    float o[10][4] = {};
#pragma unroll
    for (int kk = 0; kk < 5; kk++) {
        uint32_t ph4[4], pl4[4];
        uint32_t pa = sb + 101376 + (w * 16 + (lane & 15)) * 176 + (kk * 16 + (lane >> 4) * 8) * 2;
        LDM4(ph4, pa); LDM4(pl4, pa + 22528);
        uint32_t vh2[10][2], vl2[10][2];
#pragma unroll
        for (int njp = 0; njp < 5; njp++) {
            uint32_t va = sb + 73216 + (kk * 16 + (lane & 7) + ((lane >> 3) & 1) * 8) * 176
                        + (njp * 16 + ((lane >> 4) << 3)) * 2;
            uint32_t r[4];
            LDM4T(r, va);
            vh2[2*njp][0] = r[0]; vh2[2*njp][1] = r[1];
            vh2[2*njp+1][0] = r[2]; vh2[2*njp+1][1] = r[3];
            LDM4T(r, va + 14080);
            vl2[2*njp][0] = r[0]; vl2[2*njp][1] = r[1];
            vl2[2*njp+1][0] = r[2]; vl2[2*njp+1][1] = r[3];
        }
#pragma unroll
        for (int nj = 0; nj < 10; nj++) {
            mma_bf16(o[nj], ph4, vh2[nj]);
            mma_bf16(o[nj], ph4, vl2[nj]);
            mma_bf16(o[nj], pl4, vh2[nj]);
        }
    }
    float inv0 = 1.f / rs0, inv1 = 1.f / rs1;
    int trow = lane >> 2, tc = (lane & 3) * 2;
    long tok0 = (long)(b * 1024 + q0 + w * 16 + trow);
#pragma unroll
    for (int nj = 0; nj < 10; nj++) {
        int col = h * 80 + nj * 8 + tc;
        long idx = tok0 * 640 + col;
        float v0 = o[nj][0] * inv0, v1 = o[nj][1] * inv0;
        float v2 = o[nj][2] * inv1, v3 = o[nj][3] * inv1;
        bf16 h0 = __float2bfloat16(v0), h1 = __float2bfloat16(v1);
        bf16 h2 = __float2bfloat16(v2), h3 = __float2bfloat16(v3);
        *(__nv_bfloat162*)(oh + idx) = __halves2bfloat162(h0, h1);
        *(__nv_bfloat162*)(ol + idx) = __halves2bfloat162(
            __float2bfloat16(v0 - __bfloat162float(h0)), __float2bfloat16(v1 - __bfloat162float(h1)));
        long idx2 = idx + 8L * 640;
        *(__nv_bfloat162*)(oh + idx2) = __halves2bfloat162(h2, h3);
        *(__nv_bfloat162*)(ol + idx2) = __halves2bfloat162(
            __float2bfloat16(v2 - __bfloat162float(h2)), __float2bfloat16(v3 - __bfloat162float(h3)));
    }
}

// ---------------- host ----------------
static inline GP mkgp() { GP p; p.Ah=p.Al=p.Bh=p.Bl=nullptr; p.C=nullptr; p.bias=nullptr; p.res=nullptr;
    p.Ch=p.Cl=nullptr; p.M=p.N=p.K=p.lda=p.ldb=p.ldc=p.permute=0; p.alpha=1.f; return p; }
static inline void runG(const GP& p) {
    dim3 g((p.N + 63) / 64, (p.M + 127) / 128, 1);
    mma_gemm<<<g, 256, GEMM_SMEM>>>(p);
}

extern "C" void kernel_launch(void* const* d_in, const int* in_sizes, int n_in,
                              void* d_out, int out_size) {
    const float* x = (const float*)d_in[0];   const float* ctx = (const float*)d_in[1];
    const float* gn_s = (const float*)d_in[2];const float* gn_b = (const float*)d_in[3];
    const float* conv1_w=(const float*)d_in[4];const float* conv1_b=(const float*)d_in[5];
    const float* ln1_s=(const float*)d_in[6]; const float* ln1_b=(const float*)d_in[7];
    const float* sa_in_w=(const float*)d_in[8];const float* sa_out_w=(const float*)d_in[9];
    const float* sa_out_b=(const float*)d_in[10];
    const float* ln2_s=(const float*)d_in[11];const float* ln2_b=(const float*)d_in[12];
    const float* ca_q_w=(const float*)d_in[13];const float* ca_k_w=(const float*)d_in[14];
    const float* ca_v_w=(const float*)d_in[15];const float* ca_out_w=(const float*)d_in[16];
    const float* ca_out_b=(const float*)d_in[17];
    const float* ln3_s=(const float*)d_in[18];const float* ln3_b=(const float*)d_in[19];
    const float* lin1_w=(const float*)d_in[20];const float* lin1_b=(const float*)d_in[21];
    const float* lin2_w=(const float*)d_in[22];const float* lin2_b=(const float*)d_in[23];
    const float* co_w=(const float*)d_in[24]; const float* co_b=(const float*)d_in[25];
    float* out = (float*)d_out;

    cudaFuncSetAttribute(mma_gemm, cudaFuncAttributeMaxDynamicSharedMemorySize, GEMM_SMEM);
    cudaFuncSetAttribute(flash_sa, cudaFuncAttributeMaxDynamicSharedMemorySize, SA_SMEM);
    cudaFuncSetAttribute(flash_ca, cudaFuncAttributeMaxDynamicSharedMemorySize, CA_SMEM);

    float *pX,*pF,*pGS;
    bf16 *t1h,*t1l,*t2h,*t2l,*q2h,*q2l,*ckh,*ckl,*cvh,*cvl,*cxh,*cxl,*wh,*wl;
    cudaGetSymbolAddress((void**)&pX,g_X);  cudaGetSymbolAddress((void**)&pF,g_F);
    cudaGetSymbolAddress((void**)&pGS,g_GS);
    cudaGetSymbolAddress((void**)&t1h,g_t1h); cudaGetSymbolAddress((void**)&t1l,g_t1l);
    cudaGetSymbolAddress((void**)&t2h,g_t2h); cudaGetSymbolAddress((void**)&t2l,g_t2l);
    cudaGetSymbolAddress((void**)&q2h,g_q2h); cudaGetSymbolAddress((void**)&q2l,g_q2l);
    cudaGetSymbolAddress((void**)&ckh,g_ckh); cudaGetSymbolAddress((void**)&ckl,g_ckl);
    cudaGetSymbolAddress((void**)&cvh,g_cvh); cudaGetSymbolAddress((void**)&cvl,g_cvl);
    cudaGetSymbolAddress((void**)&cxh,g_cxh); cudaGetSymbolAddress((void**)&cxl,g_cxl);
    cudaGetSymbolAddress((void**)&wh,g_wh);   cudaGetSymbolAddress((void**)&wl,g_wl);

    dim3 tb(32, 8);
    cvt_hl<<<1600,256>>>(conv1_w, wh+0, wl+0, 409600);
    wcvtT<<<dim3(60,20),tb>>>(sa_in_w,  wh+409600,  wl+409600,  640, 1920);
    wcvtT<<<dim3(20,20),tb>>>(sa_out_w, wh+1638400, wl+1638400, 640, 640);
    wcvtT<<<dim3(20,20),tb>>>(ca_q_w,   wh+2048000, wl+2048000, 640, 640);
    wcvtT<<<dim3(20,16),tb>>>(ca_k_w,   wh+2457600, wl+2457600, 512, 640);
    wcvtT<<<dim3(20,16),tb>>>(ca_v_w,   wh+2785280, wl+2785280, 512, 640);
    wcvtT<<<dim3(20,20),tb>>>(ca_out_w, wh+3112960, wl+3112960, 640, 640);
    wcvtT<<<dim3(160,20),tb>>>(lin1_w,  wh+3522560, wl+3522560, 640, 5120);
    wcvtT<<<dim3(20,80),tb>>>(lin2_w,   wh+6799360, wl+6799360, 2560, 640);
    cvt_hl<<<1600,256>>>(co_w, wh+8437760, wl+8437760, 409600);
    cvt_hl<<<1232,256>>>(ctx, cxh, cxl, 8L*SCTX*DCTX);

    gn_stats_k<<<NB*GRP,256>>>(x, pGS);
    gn_apply_hl<<<dim3(32,20,NB),tb>>>(x, pGS, gn_s, gn_b, t1h, t1l);
    { GP p=mkgp(); p.Ah=t1h;p.Al=t1l;p.lda=640; p.Bh=wh;p.Bl=wl;p.ldb=640;
      p.M=NTOK;p.N=640;p.K=640; p.C=pX;p.ldc=640; p.bias=conv1_b; runG(p); }
    // self-attention
    layernorm_hl<<<NTOK,256>>>(pX, ln1_s, ln1_b, t1h, t1l);
    { GP p=mkgp(); p.Ah=t1h;p.Al=t1l;p.lda=640; p.Bh=wh+409600;p.Bl=wl+409600;p.ldb=640;
      p.M=NTOK;p.N=1920;p.K=640; p.Ch=q2h;p.Cl=q2l;p.ldc=1920; runG(p); }
    flash_sa<<<dim3(8,64),256,SA_SMEM>>>(q2h, q2l, t2h, t2l);
    { GP p=mkgp(); p.Ah=t2h;p.Al=t2l;p.lda=640; p.Bh=wh+1638400;p.Bl=wl+1638400;p.ldb=640;
      p.M=NTOK;p.N=640;p.K=640; p.C=pX;p.ldc=640; p.bias=sa_out_b; p.res=pX; runG(p); }
    // cross-attention
    layernorm_hl<<<NTOK,256>>>(pX, ln2_s, ln2_b, t1h, t1l);
    { GP p=mkgp(); p.Ah=t1h;p.Al=t1l;p.lda=640; p.Bh=wh+2048000;p.Bl=wl+2048000;p.ldb=640;
      p.M=NTOK;p.N=640;p.K=640; p.Ch=q2h;p.Cl=q2l;p.ldc=640; runG(p); }
    { GP p=mkgp(); p.Ah=cxh;p.Al=cxl;p.lda=512; p.Bh=wh+2457600;p.Bl=wl+2457600;p.ldb=512;
      p.M=8*SCTX;p.N=640;p.K=512; p.Ch=ckh;p.Cl=ckl;p.ldc=640; runG(p); }
    { GP p=mkgp(); p.Ah=cxh;p.Al=cxl;p.lda=512; p.Bh=wh+2785280;p.Bl=wl+2785280;p.ldb=512;
      p.M=8*SCTX;p.N=640;p.K=512; p.Ch=cvh;p.Cl=cvl;p.ldc=640; runG(p); }
    flash_ca<<<dim3(8,64),256,CA_SMEM>>>(q2h, q2l, ckh, ckl, cvh, cvl, t1h, t1l);
    { GP p=mkgp(); p.Ah=t1h;p.Al=t1l;p.lda=640; p.Bh=wh+3112960;p.Bl=wl+3112960;p.ldb=640;
      p.M=NTOK;p.N=640;p.K=640; p.C=pX;p.ldc=640; p.bias=ca_out_b; p.res=pX; runG(p); }
    // GeGLU FFN
    layernorm_hl<<<NTOK,256>>>(pX, ln3_s, ln3_b, t1h, t1l);
    { GP p=mkgp(); p.Ah=t1h;p.Al=t1l;p.lda=640; p.Bh=wh+3522560;p.Bl=wl+3522560;p.ldb=640;
      p.M=NTOK;p.N=5120;p.K=640; p.C=pF;p.ldc=5120; p.bias=lin1_b; runG(p); }
    geglu_hl<<<81920,256>>>(pF, t2h, t2l);
    { GP p=mkgp(); p.Ah=t2h;p.Al=t2l;p.lda=2560; p.Bh=wh+6799360;p.Bl=wl+6799360;p.ldb=2560;
      p.M=NTOK;p.N=640;p.K=2560; p.C=pX;p.ldc=640; p.bias=lin2_b; p.res=pX;
      p.Ch=t1h;p.Cl=t1l; runG(p); }
    // final conv + long residual (permuted NCHW)
    { GP p=mkgp(); p.Ah=t1h;p.Al=t1l;p.lda=640; p.Bh=wh+8437760;p.Bl=wl+8437760;p.ldb=640;
      p.M=NTOK;p.N=640;p.K=640; p.C=out;p.ldc=640; p.bias=co_b; p.res=x; p.permute=1; runG(p); }
}

// round 12
// speedup vs baseline: 2.3897x; 1.0015x over previous
#include <cuda_runtime.h>
#include <cuda_bf16.h>
#include <math.h>
#include <stdint.h>

#define NB 8
#define CCH 640
#define HW 1024
#define NTOK 8192
#define NH 8
#define DH 80
#define SCTX 77
#define DCTX 512
#define FF 5120
#define FFH 2560
#define GRP 32
#define CPG 20
typedef __nv_bfloat16 bf16;

// ---------------- scratch ----------------
__device__ float g_X[(long)NTOK*CCH];
__device__ float g_F[(long)NTOK*FF];
__device__ float g_GS[NB*GRP*2];
__device__ bf16 g_t1h[(long)NTOK*CCH], g_t1l[(long)NTOK*CCH];
__device__ bf16 g_t2h[(long)NTOK*FFH], g_t2l[(long)NTOK*FFH];
__device__ bf16 g_q2h[(long)NTOK*1920], g_q2l[(long)NTOK*1920];
__device__ bf16 g_ckh[8*SCTX*CCH], g_ckl[8*SCTX*CCH];
__device__ bf16 g_cvh[8*SCTX*CCH], g_cvl[8*SCTX*CCH];
__device__ bf16 g_cxh[8*SCTX*DCTX], g_cxl[8*SCTX*DCTX];
__device__ bf16 g_wh[8847360], g_wl[8847360];

__device__ __forceinline__ void wr_hl(bf16* h, bf16* l, long i, float v) {
    bf16 hh = __float2bfloat16(v);
    h[i] = hh; l[i] = __float2bfloat16(v - __bfloat162float(hh));
}
__device__ __forceinline__ void sts32(uint32_t a, uint32_t v) {
    asm volatile("st.shared.b32 [%0], %1;" :: "r"(a), "r"(v) : "memory");
}

// ---------------- small kernels ----------------
__global__ void gn_stats_k(const float* __restrict__ x, float* __restrict__ st) {
    int n = blockIdx.x >> 5, g = blockIdx.x & 31;
    const float* base = x + ((long)n * CCH + g * CPG) * HW;
    const int CNT = CPG * HW;
    float s = 0.f, s2 = 0.f;
    for (int i = threadIdx.x; i < CNT; i += 256) { float v = base[i]; s += v; s2 += v * v; }
    __shared__ float r1[256], r2[256];
    r1[threadIdx.x] = s; r2[threadIdx.x] = s2; __syncthreads();
    for (int t = 128; t > 0; t >>= 1) {
        if (threadIdx.x < t) { r1[threadIdx.x] += r1[threadIdx.x + t]; r2[threadIdx.x] += r2[threadIdx.x + t]; }
        __syncthreads();
    }
    if (threadIdx.x == 0) {
        float mu = r1[0] / CNT, var = r2[0] / CNT - mu * mu;
        st[blockIdx.x * 2] = mu; st[blockIdx.x * 2 + 1] = rsqrtf(var + 1e-6f);
    }
}
__global__ void gn_apply_hl(const float* __restrict__ x, const float* __restrict__ st,
                            const float* __restrict__ gs, const float* __restrict__ gb,
                            bf16* __restrict__ oh, bf16* __restrict__ ol) {
    __shared__ float tile[32][33];
    int n = blockIdx.z, c0 = blockIdx.y * 32, hw0 = blockIdx.x * 32;
    int tx = threadIdx.x, ty = threadIdx.y;
#pragma unroll
    for (int j = 0; j < 4; j++) {
        int c = c0 + ty + j * 8;
        float v = x[((long)n * CCH + c) * HW + hw0 + tx];
        int g = c / CPG;
        tile[ty + j * 8][tx] = (v - st[(n * GRP + g) * 2]) * st[(n * GRP + g) * 2 + 1] * gs[c] + gb[c];
    }
    __syncthreads();
#pragma unroll
    for (int j = 0; j < 4; j++) {
        int hw = hw0 + ty + j * 8;
        wr_hl(oh, ol, ((long)n * HW + hw) * CCH + c0 + tx, tile[tx][ty + j * 8]);
    }
}
__global__ void layernorm_hl(const float* __restrict__ X, const float* __restrict__ s,
                             const float* __restrict__ b, bf16* __restrict__ oh, bf16* __restrict__ ol) {
    long row = blockIdx.x;
    const float* p = X + row * CCH;
    int tid = threadIdx.x;
    float v[3]; int c = 0; float sm = 0.f, s2 = 0.f;
    for (int i = tid; i < CCH; i += 256) { float t = p[i]; v[c++] = t; sm += t; s2 += t * t; }
    __shared__ float r1[256], r2[256];
    r1[tid] = sm; r2[tid] = s2; __syncthreads();
    for (int t = 128; t > 0; t >>= 1) {
        if (tid < t) { r1[tid] += r1[tid + t]; r2[tid] += r2[tid + t]; }
        __syncthreads();
    }
    float mu = r1[0] / CCH, rstd = rsqrtf(r2[0] / CCH - mu * mu + 1e-5f);
    c = 0;
    for (int i = tid; i < CCH; i += 256)
        wr_hl(oh, ol, row * CCH + i, (v[c++] - mu) * rstd * s[i] + b[i]);
}
__global__ void cvt_hl(const float* __restrict__ x, bf16* __restrict__ h, bf16* __restrict__ l, long n) {
    long i = (long)blockIdx.x * 256 + threadIdx.x;
    if (i < n) wr_hl(h, l, i, x[i]);
}
__global__ void wcvtT(const float* __restrict__ w, bf16* __restrict__ oh, bf16* __restrict__ ol, int K, int N) {
    __shared__ float t[32][33];
    int n0 = blockIdx.x * 32, k0 = blockIdx.y * 32;
    int tx = threadIdx.x, ty = threadIdx.y;
#pragma unroll
    for (int j = 0; j < 4; j++) {
        int k = k0 + ty + j * 8;
        t[ty + j * 8][tx] = (k < K && n0 + tx < N) ? w[(long)k * N + n0 + tx] : 0.f;
    }
    __syncthreads();
#pragma unroll
    for (int j = 0; j < 4; j++) {
        int n = n0 + ty + j * 8, k = k0 + tx;
        if (n < N && k < K) wr_hl(oh, ol, (long)n * K + k, t[tx][ty + j * 8]);
    }
}
__global__ void geglu_hl(const float* __restrict__ F, bf16* __restrict__ oh, bf16* __restrict__ ol) {
    long i = (long)blockIdx.x * 256 + threadIdx.x;
    if (i >= (long)NTOK * FFH) return;
    long row = i / FFH; int col = (int)(i % FFH);
    float a = F[row * FF + col], g = F[row * FF + FFH + col];
    wr_hl(oh, ol, i, a * (0.5f * g * (1.0f + erff(g * 0.70710678118654752f))));
}

// ---------------- HMMA primitives ----------------
#define LDM4(r, a) asm volatile("ldmatrix.sync.aligned.m8n8.x4.shared.b16 {%0,%1,%2,%3}, [%4];" \
    : "=r"((r)[0]), "=r"((r)[1]), "=r"((r)[2]), "=r"((r)[3]) : "r"(a))
#define LDM4T(r, a) asm volatile("ldmatrix.sync.aligned.m8n8.x4.trans.shared.b16 {%0,%1,%2,%3}, [%4];" \
    : "=r"((r)[0]), "=r"((r)[1]), "=r"((r)[2]), "=r"((r)[3]) : "r"(a))

__device__ __forceinline__ void mma_bf16(float* d, const uint32_t* a, const uint32_t* b) {
    asm volatile("mma.sync.aligned.m16n8k16.row.col.f32.bf16.bf16.f32 "
        "{%0,%1,%2,%3}, {%4,%5,%6,%7}, {%8,%9}, {%0,%1,%2,%3};"
        : "+f"(d[0]), "+f"(d[1]), "+f"(d[2]), "+f"(d[3])
        : "r"(a[0]), "r"(a[1]), "r"(a[2]), "r"(a[3]), "r"(b[0]), "r"(b[1]));
}
#define CPA16(dst, src) asm volatile("cp.async.cg.shared.global [%0],[%1],16;" :: "r"(dst), "l"(src))
#define CPA16Z(dst, src, vsz) asm volatile("cp.async.cg.shared.global [%0],[%1],16,%2;" :: "r"(dst), "l"(src), "r"(vsz))
#define CPCOMMIT() asm volatile("cp.async.commit_group;")
#define CPWAIT0()  asm volatile("cp.async.wait_group 0;")
#define CPWAIT1()  asm volatile("cp.async.wait_group 1;")

// ---------------- bf16x3 dense GEMM: 128x64 tile, BK=32, 3-stage, occ 2 ----------------
struct GP {
    const bf16 *Ah, *Al, *Bh, *Bl;
    float* C; const float *bias, *res;
    bf16 *Ch, *Cl;
    int M, N, K, lda, ldb, ldc, permute;
    float alpha;
};
#define ARO 80            // smem row bytes (32 bf16 + pad)
#define A_MAT 10240       // 128*80
#define B_MAT 5120        // 64*80
#define BOFF  20480       // B base within stage
#define STG   30720
#define GEMM_SMEM (3*STG) // 92160

__global__ __launch_bounds__(256, 2) void mma_gemm(GP p) {
    extern __shared__ char smem[];
    uint32_t sb = (uint32_t)__cvta_generic_to_shared(smem);
    int tid = threadIdx.x, lane = tid & 31, wid = tid >> 5;
    int wm = wid & 3, wn = wid >> 2;       // 4x2 warp grid; warp tile 32x32
    const bf16 *Ah = p.Ah, *Al = p.Al, *Bh = p.Bh, *Bl = p.Bl;
    int m0 = blockIdx.y * 128, n0 = blockIdx.x * 64;
    int rowsA = p.M - m0; if (rowsA > 128) rowsA = 128;
    int rowsB = p.N - n0; if (rowsB > 64) rowsB = 64;

    float acc[2][4][4] = {};
    int nkb = p.K >> 5;   // all K are multiples of 32

    auto load_stage = [&](int kb, int s) {
        int k0 = kb << 5;
        uint32_t base = sb + (uint32_t)s * STG;
#pragma unroll
        for (int i = 0; i < 6; i++) {
            int c = tid + (i << 8);
            if (c < 1024) {                      // A hi/lo: 2 x 512 chunks
                int mat = c >> 9, cc = c & 511;
                int r = cc >> 2, ch = cc & 3;
                const bf16* src = (mat ? Al : Ah) + (long)(m0 + (r < rowsA ? r : 0)) * p.lda + k0 + ch * 8;
                CPA16Z(base + mat * A_MAT + r * ARO + ch * 16, src, (r < rowsA) ? 16 : 0);
            } else {                              // B hi/lo: 2 x 256 chunks
                int c2 = c - 1024;
                int mat = c2 >> 8, cc = c2 & 255;
                int r = cc >> 2, ch = cc & 3;
                const bf16* src = (mat ? Bl : Bh) + (long)(n0 + (r < rowsB ? r : 0)) * p.ldb + k0 + ch * 8;
                CPA16Z(base + BOFF + mat * B_MAT + r * ARO + ch * 16, src, (r < rowsB) ? 16 : 0);
            }
        }
        CPCOMMIT();
    };

    load_stage(0, 0);
    load_stage(1, 1);
    int slot = 0;
    for (int kb = 0; kb < nkb; kb++) {
        if (kb == nkb - 1) { CPWAIT0(); } else { CPWAIT1(); }
        __syncthreads();
        if (kb + 2 < nkb) {
            int s2 = slot + 2; if (s2 >= 3) s2 -= 3;
            load_stage(kb + 2, s2);
        }
        uint32_t stb = sb + (uint32_t)slot * STG;
#pragma unroll
        for (int kh = 0; kh < 2; kh++) {
            uint32_t ah[2][4], al[2][4], bh[4][2], bl[4][2];
            int arow = wm * 32 + (lane & 15);
            uint32_t aB = (uint32_t)((kh * 16 + (lane >> 4) * 8) * 2);
#pragma unroll
            for (int mi = 0; mi < 2; mi++) {
                uint32_t ad = stb + (arow + mi * 16) * ARO + aB;
                LDM4(ah[mi], ad);
                LDM4(al[mi], ad + A_MAT);
            }
            int brow = wn * 32 + (lane & 7) + ((lane >> 4) << 3);
            uint32_t bB = (uint32_t)((kh * 16 + ((lane >> 3) & 1) * 8) * 2);
#pragma unroll
            for (int njp = 0; njp < 2; njp++) {
                uint32_t bd = stb + BOFF + (brow + njp * 16) * ARO + bB;
                uint32_t r[4];
                LDM4(r, bd);
                bh[2*njp][0] = r[0]; bh[2*njp][1] = r[1];
                bh[2*njp+1][0] = r[2]; bh[2*njp+1][1] = r[3];
                LDM4(r, bd + B_MAT);
                bl[2*njp][0] = r[0]; bl[2*njp][1] = r[1];
                bl[2*njp+1][0] = r[2]; bl[2*njp+1][1] = r[3];
            }
#pragma unroll
            for (int mi = 0; mi < 2; mi++)
#pragma unroll
                for (int nj = 0; nj < 4; nj++) {
                    mma_bf16(acc[mi][nj], ah[mi], bh[nj]);
                    mma_bf16(acc[mi][nj], ah[mi], bl[nj]);
                    mma_bf16(acc[mi][nj], al[mi], bh[nj]);
                }
        }
        if (++slot == 3) slot = 0;
    }

    int trow = lane >> 2, tcol = (lane & 3) * 2;
#pragma unroll
    for (int mi = 0; mi < 2; mi++) {
#pragma unroll
        for (int nj = 0; nj < 4; nj++) {
#pragma unroll
            for (int e = 0; e < 4; e++) {
                int gm = m0 + wm * 32 + mi * 16 + trow + ((e >> 1) << 3);
                int gn = n0 + wn * 32 + nj * 8 + tcol + (e & 1);
                if (gm >= p.M || gn >= p.N) continue;
                float v = p.alpha * acc[mi][nj][e];
                if (p.bias) v += __ldg(p.bias + gn);
                long idx;
                if (p.permute) idx = ((long)(gm >> 10) * CCH + gn) * HW + (gm & 1023);
                else idx = (long)gm * p.ldc + gn;
                if (p.res) v += p.res[idx];
                if (p.C) p.C[idx] = v;
                if (p.Ch) wr_hl(p.Ch, p.Cl, idx, v);
            }
        }
    }
}

// ---------------- flash self-attention ----------------
// grid (8 qblocks, 64 z), 256 threads. V loaded token-major; PV uses ldmatrix.trans.
// smem: Qh 0 / Ql 22528 (128x176B); K stage s: 45056+s*22528 (hi, lo +11264), 64x176B
//       V stage s: 90112+s*22528 (hi, lo +11264), 64 keys x 176B (80 d)
//       Ph 135168 / Pl 153600 (128x144B). total 172032
#define SA_SMEM 172032
#define ISQ 0.11180339887498949f

__global__ __launch_bounds__(256, 1) void flash_sa(
    const bf16* __restrict__ qh, const bf16* __restrict__ ql,
    bf16* __restrict__ oh, bf16* __restrict__ ol)
{
    extern __shared__ char smem[];
    uint32_t sb = (uint32_t)__cvta_generic_to_shared(smem);
    const uint32_t Qhb = sb, Qlb = sb + 22528;
    int tid = threadIdx.x, lane = tid & 31, w = tid >> 5;
    int z = blockIdx.y, b = z >> 3, h = z & 7;
    int q0 = blockIdx.x * 128;
    const bf16* Qh_src = qh + ((long)(b * 1024 + q0)) * 1920 + h * 80;
    const bf16* Ql_src = ql + ((long)(b * 1024 + q0)) * 1920 + h * 80;
    const bf16* Kh_src = qh + ((long)b * 1024) * 1920 + 640 + h * 80;
    const bf16* Kl_src = ql + ((long)b * 1024) * 1920 + 640 + h * 80;
    const bf16* Vh_src = qh + ((long)b * 1024) * 1920 + 1280 + h * 80;
    const bf16* Vl_src = ql + ((long)b * 1024) * 1920 + 1280 + h * 80;

    for (int c = tid; c < 1280; c += 256) {
        int r = c / 10, ch = c - r * 10;
        CPA16(Qhb + r * 176 + ch * 16, Qh_src + (long)r * 1920 + ch * 8);
        CPA16(Qlb + r * 176 + ch * 16, Ql_src + (long)r * 1920 + ch * 8);
    }
    auto load_kv = [&](int kb, int s) {
        uint32_t Kb = sb + 45056 + s * 22528;
        uint32_t Vb = sb + 90112 + s * 22528;
        const bf16* kh = Kh_src + (long)(kb * 64) * 1920;
        const bf16* kl = Kl_src + (long)(kb * 64) * 1920;
        const bf16* vh = Vh_src + (long)(kb * 64) * 1920;
        const bf16* vl = Vl_src + (long)(kb * 64) * 1920;
        for (int c = tid; c < 640; c += 256) {
            int r = c / 10, ch = c - r * 10;
            CPA16(Kb + r * 176 + ch * 16, kh + (long)r * 1920 + ch * 8);
            CPA16(Kb + 11264 + r * 176 + ch * 16, kl + (long)r * 1920 + ch * 8);
            CPA16(Vb + r * 176 + ch * 16, vh + (long)r * 1920 + ch * 8);
            CPA16(Vb + 11264 + r * 176 + ch * 16, vl + (long)r * 1920 + ch * 8);
        }
    };
    load_kv(0, 0);
    CPCOMMIT();

    float m_[2] = {-1e30f, -1e30f}, l_[2] = {0.f, 0.f};
    float o[10][4] = {};
    int prow = w * 16 + (lane >> 2), pc0 = (lane & 3) * 2;

    for (int kb = 0; kb < 16; kb++) {
        int s = kb & 1;
        CPWAIT0();
        __syncthreads();
        if (kb + 1 < 16) { load_kv(kb + 1, s ^ 1); CPCOMMIT(); }
        uint32_t Kb = sb + 45056 + s * 22528;
        uint32_t Vb = sb + 90112 + s * 22528;
        // ---- S = Q K^T ----
        float sacc[8][4] = {};
#pragma unroll
        for (int kk = 0; kk < 5; kk++) {
            uint32_t ah[4], al[4];
            uint32_t aaddr = Qhb + (w * 16 + (lane & 15)) * 176 + (kk * 16 + (lane >> 4) * 8) * 2;
            LDM4(ah, aaddr); LDM4(al, aaddr + 22528);
            uint32_t bh[8][2], bl[8][2];
#pragma unroll
            for (int njp = 0; njp < 4; njp++) {
                uint32_t baddr = Kb + (njp * 16 + (lane & 7) + ((lane >> 4) << 3)) * 176
                               + (kk * 16 + ((lane >> 3) & 1) * 8) * 2;
                uint32_t r[4];
                LDM4(r, baddr);
                bh[2*njp][0] = r[0]; bh[2*njp][1] = r[1];
                bh[2*njp+1][0] = r[2]; bh[2*njp+1][1] = r[3];
                LDM4(r, baddr + 11264);
                bl[2*njp][0] = r[0]; bl[2*njp][1] = r[1];
                bl[2*njp+1][0] = r[2]; bl[2*njp+1][1] = r[3];
            }
#pragma unroll
            for (int nj = 0; nj < 8; nj++) {
                mma_bf16(sacc[nj], ah, bh[nj]);
                mma_bf16(sacc[nj], ah, bl[nj]);
                mma_bf16(sacc[nj], al, bh[nj]);
            }
        }
        // ---- online softmax ----
        float mx0 = -1e30f, mx1 = -1e30f;
#pragma unroll
        for (int nj = 0; nj < 8; nj++) {
            mx0 = fmaxf(mx0, fmaxf(sacc[nj][0], sacc[nj][1]));
            mx1 = fmaxf(mx1, fmaxf(sacc[nj][2], sacc[nj][3]));
        }
        mx0 = fmaxf(mx0, __shfl_xor_sync(0xffffffff, mx0, 1));
        mx0 = fmaxf(mx0, __shfl_xor_sync(0xffffffff, mx0, 2));
        mx1 = fmaxf(mx1, __shfl_xor_sync(0xffffffff, mx1, 1));
        mx1 = fmaxf(mx1, __shfl_xor_sync(0xffffffff, mx1, 2));
        float mn0 = fmaxf(m_[0], mx0 * ISQ), mn1 = fmaxf(m_[1], mx1 * ISQ);
        float sc0 = __expf(m_[0] - mn0), sc1 = __expf(m_[1] - mn1);
        m_[0] = mn0; m_[1] = mn1;
        float rs0 = 0.f, rs1 = 0.f;
#pragma unroll
        for (int nj = 0; nj < 8; nj++) {
            float p0 = __expf(sacc[nj][0] * ISQ - mn0);
            float p1 = __expf(sacc[nj][1] * ISQ - mn0);
            float p2 = __expf(sacc[nj][2] * ISQ - mn1);
            float p3 = __expf(sacc[nj][3] * ISQ - mn1);
            rs0 += p0 + p1; rs1 += p2 + p3;
            uint32_t a0 = sb + 135168 + prow * 144 + (nj * 8 + pc0) * 2;
            uint32_t a1 = a0 + 8 * 144;
            bf16 h0 = __float2bfloat16(p0), h1 = __float2bfloat16(p1);
            bf16 h2 = __float2bfloat16(p2), h3 = __float2bfloat16(p3);
            union { __nv_bfloat162 v; uint32_t u; } c0, c1, d0, d1;
            c0.v = __halves2bfloat162(h0, h1);
            c1.v = __halves2bfloat162(h2, h3);
            d0.v = __halves2bfloat162(__float2bfloat16(p0 - __bfloat162float(h0)),
                                      __float2bfloat16(p1 - __bfloat162float(h1)));
            d1.v = __halves2bfloat162(__float2bfloat16(p2 - __bfloat162float(h2)),
                                      __float2bfloat16(p3 - __bfloat162float(h3)));
            sts32(a0, c0.u); sts32(a1, c1.u);
            sts32(a0 + 18432, d0.u); sts32(a1 + 18432, d1.u);
        }
        rs0 += __shfl_xor_sync(0xffffffff, rs0, 1);
        rs0 += __shfl_xor_sync(0xffffffff, rs0, 2);
        rs1 += __shfl_xor_sync(0xffffffff, rs1, 1);
        rs1 += __shfl_xor_sync(0xffffffff, rs1, 2);
        l_[0] = l_[0] * sc0 + rs0; l_[1] = l_[1] * sc1 + rs1;
#pragma unroll
        for (int nj = 0; nj < 10; nj++) {
            o[nj][0] *= sc0; o[nj][1] *= sc0; o[nj][2] *= sc1; o[nj][3] *= sc1;
        }
        __syncwarp();
        // ---- O += P V  (V token-major, ldmatrix.trans) ----
#pragma unroll
        for (int kk = 0; kk < 4; kk++) {
            uint32_t ph4[4], pl4[4];
            uint32_t pa = sb + 135168 + (w * 16 + (lane & 15)) * 144 + (kk * 16 + (lane >> 4) * 8) * 2;
            LDM4(ph4, pa); LDM4(pl4, pa + 18432);
            uint32_t vh2[10][2], vl2[10][2];
#pragma unroll
            for (int njp = 0; njp < 5; njp++) {
                uint32_t va = Vb + (kk * 16 + (lane & 7) + ((lane >> 3) & 1) * 8) * 176
                            + (njp * 16 + ((lane >> 4) << 3)) * 2;
                uint32_t r[4];
                LDM4T(r, va);
                vh2[2*njp][0] = r[0]; vh2[2*njp][1] = r[1];
                vh2[2*njp+1][0] = r[2]; vh2[2*njp+1][1] = r[3];
                LDM4T(r, va + 11264);
                vl2[2*njp][0] = r[0]; vl2[2*njp][1] = r[1];
                vl2[2*njp+1][0] = r[2]; vl2[2*njp+1][1] = r[3];
            }
#pragma unroll
            for (int nj = 0; nj < 10; nj++) {
                mma_bf16(o[nj], ph4, vh2[nj]);
                mma_bf16(o[nj], ph4, vl2[nj]);
                mma_bf16(o[nj], pl4, vh2[nj]);
            }
        }
        __syncwarp();
    }
    float inv0 = 1.f / l_[0], inv1 = 1.f / l_[1];
    int trow = lane >> 2, tc = (lane & 3) * 2;
    long tok0 = (long)(b * 1024 + q0 + w * 16 + trow);
#pragma unroll
    for (int nj = 0; nj < 10; nj++) {
        int col = h * 80 + nj * 8 + tc;
        long idx = tok0 * 640 + col;
        float v0 = o[nj][0] * inv0, v1 = o[nj][1] * inv0;
        float v2 = o[nj][2] * inv1, v3 = o[nj][3] * inv1;
        bf16 h0 = __float2bfloat16(v0), h1 = __float2bfloat16(v1);
        bf16 h2 = __float2bfloat16(v2), h3 = __float2bfloat16(v3);
        *(__nv_bfloat162*)(oh + idx) = __halves2bfloat162(h0, h1);
        *(__nv_bfloat162*)(ol + idx) = __halves2bfloat162(
            __float2bfloat16(v0 - __bfloat162float(h0)), __float2bfloat16(v1 - __bfloat162float(h1)));
        long idx2 = idx + 8L * 640;
        *(__nv_bfloat162*)(oh + idx2) = __halves2bfloat162(h2, h3);
        *(__nv_bfloat162*)(ol + idx2) = __halves2bfloat162(
            __float2bfloat16(v2 - __bfloat162float(h2)), __float2bfloat16(v3 - __bfloat162float(h3)));
    }
}

// ---------------- flash cross-attention (77 keys) ----------------
// smem: Qh 0/Ql 22528; Kh 45056/Kl 59136 (80x176); Vh 73216/Vl 87296 (80 keys x 176, token-major);
//       Ph 101376/Pl 123904 (128x176). total 146432
#define CA_SMEM 146432
__global__ __launch_bounds__(256, 1) void flash_ca(
    const bf16* __restrict__ qh, const bf16* __restrict__ ql,
    const bf16* __restrict__ kh, const bf16* __restrict__ kl,
    const bf16* __restrict__ vh, const bf16* __restrict__ vl,
    bf16* __restrict__ oh, bf16* __restrict__ ol)
{
    extern __shared__ char smem[];
    uint32_t sb = (uint32_t)__cvta_generic_to_shared(smem);
    int tid = threadIdx.x, lane = tid & 31, w = tid >> 5;
    int z = blockIdx.y, b = z >> 3, h = z & 7;
    int q0 = blockIdx.x * 128;
    const bf16* Qh_src = qh + ((long)(b * 1024 + q0)) * 640 + h * 80;
    const bf16* Ql_src = ql + ((long)(b * 1024 + q0)) * 640 + h * 80;
    const bf16* Kh_src = kh + ((long)(b * SCTX)) * 640 + h * 80;
    const bf16* Kl_src = kl + ((long)(b * SCTX)) * 640 + h * 80;
    const bf16* Vh_src = vh + ((long)(b * SCTX)) * 640 + h * 80;
    const bf16* Vl_src = vl + ((long)(b * SCTX)) * 640 + h * 80;

    for (int c = tid; c < 1280; c += 256) {
        int r = c / 10, ch = c - r * 10;
        CPA16(sb + r * 176 + ch * 16, Qh_src + (long)r * 640 + ch * 8);
        CPA16(sb + 22528 + r * 176 + ch * 16, Ql_src + (long)r * 640 + ch * 8);
    }
    for (int c = tid; c < 800; c += 256) {
        int r = c / 10, ch = c - r * 10;
        int vsz = (r < SCTX) ? 16 : 0;
        int rc = (r < SCTX) ? r : 0;
        CPA16Z(sb + 45056 + r * 176 + ch * 16, Kh_src + (long)rc * 640 + ch * 8, vsz);
        CPA16Z(sb + 59136 + r * 176 + ch * 16, Kl_src + (long)rc * 640 + ch * 8, vsz);
        CPA16Z(sb + 73216 + r * 176 + ch * 16, Vh_src + (long)rc * 640 + ch * 8, vsz);
        CPA16Z(sb + 87296 + r * 176 + ch * 16, Vl_src + (long)rc * 640 + ch * 8, vsz);
    }
    CPCOMMIT(); CPWAIT0();
    __syncthreads();

    float sacc[10][4] = {};
#pragma unroll
    for (int kk = 0; kk < 5; kk++) {
        uint32_t ah[4], al[4];
        uint32_t aaddr = sb + (w * 16 + (lane & 15)) * 176 + (kk * 16 + (lane >> 4) * 8) * 2;
        LDM4(ah, aaddr); LDM4(al, aaddr + 22528);
        uint32_t bh[10][2], bl[10][2];
#pragma unroll
        for (int njp = 0; njp < 5; njp++) {
            uint32_t baddr = sb + 45056 + (njp * 16 + (lane & 7) + ((lane >> 4) << 3)) * 176
                           + (kk * 16 + ((lane >> 3) & 1) * 8) * 2;
            uint32_t r[4];
            LDM4(r, baddr);
            bh[2*njp][0] = r[0]; bh[2*njp][1] = r[1];
            bh[2*njp+1][0] = r[2]; bh[2*njp+1][1] = r[3];
            LDM4(r, baddr + 14080);
            bl[2*njp][0] = r[0]; bl[2*njp][1] = r[1];
            bl[2*njp+1][0] = r[2]; bl[2*njp+1][1] = r[3];
        }
#pragma unroll
        for (int nj = 0; nj < 10; nj++) {
            mma_bf16(sacc[nj], ah, bh[nj]);
            mma_bf16(sacc[nj], ah, bl[nj]);
            mma_bf16(sacc[nj], al, bh[nj]);
        }
    }
    int pc0 = (lane & 3) * 2;
#pragma unroll
    for (int nj = 0; nj < 10; nj++)
#pragma unroll
        for (int e = 0; e < 4; e++) {
            int col = nj * 8 + pc0 + (e & 1);
            if (col >= SCTX) sacc[nj][e] = -1e30f;
        }
    float mx0 = -1e30f, mx1 = -1e30f;
#pragma unroll
    for (int nj = 0; nj < 10; nj++) {
        mx0 = fmaxf(mx0, fmaxf(sacc[nj][0], sacc[nj][1]));
        mx1 = fmaxf(mx1, fmaxf(sacc[nj][2], sacc[nj][3]));
    }
    mx0 = fmaxf(mx0, __shfl_xor_sync(0xffffffff, mx0, 1));
    mx0 = fmaxf(mx0, __shfl_xor_sync(0xffffffff, mx0, 2));
    mx1 = fmaxf(mx1, __shfl_xor_sync(0xffffffff, mx1, 1));
    mx1 = fmaxf(mx1, __shfl_xor_sync(0xffffffff, mx1, 2));
    mx0 *= ISQ; mx1 *= ISQ;
    float rs0 = 0.f, rs1 = 0.f;
    int prow = w * 16 + (lane >> 2);
#pragma unroll
    for (int nj = 0; nj < 10; nj++) {
        float p0 = __expf(sacc[nj][0] * ISQ - mx0);
        float p1 = __expf(sacc[nj][1] * ISQ - mx0);
        float p2 = __expf(sacc[nj][2] * ISQ - mx1);
        float p3 = __expf(sacc[nj][3] * ISQ - mx1);
        rs0 += p0 + p1; rs1 += p2 + p3;
        uint32_t a0 = sb + 101376 + prow * 176 + (nj * 8 + pc0) * 2;
        uint32_t a1 = a0 + 8 * 176;
        bf16 h0 = __float2bfloat16(p0), h1 = __float2bfloat16(p1);
        bf16 h2 = __float2bfloat16(p2), h3 = __float2bfloat16(p3);
        union { __nv_bfloat162 v; uint32_t u; } c0, c1, d0, d1;
        c0.v = __halves2bfloat162(h0, h1);
        c1.v = __halves2bfloat162(h2, h3);
        d0.v = __halves2bfloat162(__float2bfloat16(p0 - __bfloat162float(h0)),
                                  __float2bfloat16(p1 - __bfloat162float(h1)));
        d1.v = __halves2bfloat162(__float2bfloat16(p2 - __bfloat162float(h2)),
                                  __float2bfloat16(p3 - __bfloat162float(h3)));
        sts32(a0, c0.u); sts32(a1, c1.u);
        sts32(a0 + 22528, d0.u); sts32(a1 + 22528, d1.u);
    }
    rs0 += __shfl_xor_sync(0xffffffff, rs0, 1);
    rs0 += __shfl_xor_sync(0xffffffff, rs0, 2);
    rs1 += __shfl_xor_sync(0xffffffff, rs1, 1);
    rs1 += __shfl_xor_sync(0xffffffff, rs1, 2);
    __syncwarp();
    float o[10][4] = {};
#pragma unroll
    for (int kk = 0; kk < 5; kk++) {
        uint32_t ph4[4], pl4[4];
        uint32_t pa = sb + 101376 + (w * 16 + (lane & 15)) * 176 + (kk * 16 + (lane >> 4) * 8) * 2;
        LDM4(ph4, pa); LDM4(pl4, pa + 22528);
        uint32_t vh2[10][2], vl2[10][2];
#pragma unroll
        for (int njp = 0; njp < 5; njp++) {
            uint32_t va = sb + 73216 + (kk * 16 + (lane & 7) + ((lane >> 3) & 1) * 8) * 176
                        + (njp * 16 + ((lane >> 4) << 3)) * 2;
            uint32_t r[4];
            LDM4T(r, va);
            vh2[2*njp][0] = r[0]; vh2[2*njp][1] = r[1];
            vh2[2*njp+1][0] = r[2]; vh2[2*njp+1][1] = r[3];
            LDM4T(r, va + 14080);
            vl2[2*njp][0] = r[0]; vl2[2*njp][1] = r[1];
            vl2[2*njp+1][0] = r[2]; vl2[2*njp+1][1] = r[3];
        }
#pragma unroll
        for (int nj = 0; nj < 10; nj++) {
            mma_bf16(o[nj], ph4, vh2[nj]);
            mma_bf16(o[nj], ph4, vl2[nj]);
            mma_bf16(o[nj], pl4, vh2[nj]);
        }
    }
    float inv0 = 1.f / rs0, inv1 = 1.f / rs1;
    int trow = lane >> 2, tc = (lane & 3) * 2;
    long tok0 = (long)(b * 1024 + q0 + w * 16 + trow);
#pragma unroll
    for (int nj = 0; nj < 10; nj++) {
        int col = h * 80 + nj * 8 + tc;
        long idx = tok0 * 640 + col;
        float v0 = o[nj][0] * inv0, v1 = o[nj][1] * inv0;
        float v2 = o[nj][2] * inv1, v3 = o[nj][3] * inv1;
        bf16 h0 = __float2bfloat16(v0), h1 = __float2bfloat16(v1);
        bf16 h2 = __float2bfloat16(v2), h3 = __float2bfloat16(v3);
        *(__nv_bfloat162*)(oh + idx) = __halves2bfloat162(h0, h1);
        *(__nv_bfloat162*)(ol + idx) = __halves2bfloat162(
            __float2bfloat16(v0 - __bfloat162float(h0)), __float2bfloat16(v1 - __bfloat162float(h1)));
        long idx2 = idx + 8L * 640;
        *(__nv_bfloat162*)(oh + idx2) = __halves2bfloat162(h2, h3);
        *(__nv_bfloat162*)(ol + idx2) = __halves2bfloat162(
            __float2bfloat16(v2 - __bfloat162float(h2)), __float2bfloat16(v3 - __bfloat162float(h3)));
    }
}

// ---------------- host ----------------
static inline GP mkgp() { GP p; p.Ah=p.Al=p.Bh=p.Bl=nullptr; p.C=nullptr; p.bias=nullptr; p.res=nullptr;
    p.Ch=p.Cl=nullptr; p.M=p.N=p.K=p.lda=p.ldb=p.ldc=p.permute=0; p.alpha=1.f; return p; }
static inline void runG(const GP& p) {
    dim3 g((p.N + 63) / 64, (p.M + 127) / 128, 1);
    mma_gemm<<<g, 256, GEMM_SMEM>>>(p);
}

extern "C" void kernel_launch(void* const* d_in, const int* in_sizes, int n_in,
                              void* d_out, int out_size) {
    const float* x = (const float*)d_in[0];   const float* ctx = (const float*)d_in[1];
    const float* gn_s = (const float*)d_in[2];const float* gn_b = (const float*)d_in[3];
    const float* conv1_w=(const float*)d_in[4];const float* conv1_b=(const float*)d_in[5];
    const float* ln1_s=(const float*)d_in[6]; const float* ln1_b=(const float*)d_in[7];
    const float* sa_in_w=(const float*)d_in[8];const float* sa_out_w=(const float*)d_in[9];
    const float* sa_out_b=(const float*)d_in[10];
    const float* ln2_s=(const float*)d_in[11];const float* ln2_b=(const float*)d_in[12];
    const float* ca_q_w=(const float*)d_in[13];const float* ca_k_w=(const float*)d_in[14];
    const float* ca_v_w=(const float*)d_in[15];const float* ca_out_w=(const float*)d_in[16];
    const float* ca_out_b=(const float*)d_in[17];
    const float* ln3_s=(const float*)d_in[18];const float* ln3_b=(const float*)d_in[19];
    const float* lin1_w=(const float*)d_in[20];const float* lin1_b=(const float*)d_in[21];
    const float* lin2_w=(const float*)d_in[22];const float* lin2_b=(const float*)d_in[23];
    const float* co_w=(const float*)d_in[24]; const float* co_b=(const float*)d_in[25];
    float* out = (float*)d_out;

    cudaFuncSetAttribute(mma_gemm, cudaFuncAttributeMaxDynamicSharedMemorySize, GEMM_SMEM);
    cudaFuncSetAttribute(flash_sa, cudaFuncAttributeMaxDynamicSharedMemorySize, SA_SMEM);
    cudaFuncSetAttribute(flash_ca, cudaFuncAttributeMaxDynamicSharedMemorySize, CA_SMEM);

    float *pX,*pF,*pGS;
    bf16 *t1h,*t1l,*t2h,*t2l,*q2h,*q2l,*ckh,*ckl,*cvh,*cvl,*cxh,*cxl,*wh,*wl;
    cudaGetSymbolAddress((void**)&pX,g_X);  cudaGetSymbolAddress((void**)&pF,g_F);
    cudaGetSymbolAddress((void**)&pGS,g_GS);
    cudaGetSymbolAddress((void**)&t1h,g_t1h); cudaGetSymbolAddress((void**)&t1l,g_t1l);
    cudaGetSymbolAddress((void**)&t2h,g_t2h); cudaGetSymbolAddress((void**)&t2l,g_t2l);
    cudaGetSymbolAddress((void**)&q2h,g_q2h); cudaGetSymbolAddress((void**)&q2l,g_q2l);
    cudaGetSymbolAddress((void**)&ckh,g_ckh); cudaGetSymbolAddress((void**)&ckl,g_ckl);
    cudaGetSymbolAddress((void**)&cvh,g_cvh); cudaGetSymbolAddress((void**)&cvl,g_cvl);
    cudaGetSymbolAddress((void**)&cxh,g_cxh); cudaGetSymbolAddress((void**)&cxl,g_cxl);
    cudaGetSymbolAddress((void**)&wh,g_wh);   cudaGetSymbolAddress((void**)&wl,g_wl);

    dim3 tb(32, 8);
    cvt_hl<<<1600,256>>>(conv1_w, wh+0, wl+0, 409600);
    wcvtT<<<dim3(60,20),tb>>>(sa_in_w,  wh+409600,  wl+409600,  640, 1920);
    wcvtT<<<dim3(20,20),tb>>>(sa_out_w, wh+1638400, wl+1638400, 640, 640);
    wcvtT<<<dim3(20,20),tb>>>(ca_q_w,   wh+2048000, wl+2048000, 640, 640);
    wcvtT<<<dim3(20,16),tb>>>(ca_k_w,   wh+2457600, wl+2457600, 512, 640);
    wcvtT<<<dim3(20,16),tb>>>(ca_v_w,   wh+2785280, wl+2785280, 512, 640);
    wcvtT<<<dim3(20,20),tb>>>(ca_out_w, wh+3112960, wl+3112960, 640, 640);
    wcvtT<<<dim3(160,20),tb>>>(lin1_w,  wh+3522560, wl+3522560, 640, 5120);
    wcvtT<<<dim3(20,80),tb>>>(lin2_w,   wh+6799360, wl+6799360, 2560, 640);
    cvt_hl<<<1600,256>>>(co_w, wh+8437760, wl+8437760, 409600);
    cvt_hl<<<1232,256>>>(ctx, cxh, cxl, 8L*SCTX*DCTX);

    gn_stats_k<<<NB*GRP,256>>>(x, pGS);
    gn_apply_hl<<<dim3(32,20,NB),tb>>>(x, pGS, gn_s, gn_b, t1h, t1l);
    { GP p=mkgp(); p.Ah=t1h;p.Al=t1l;p.lda=640; p.Bh=wh;p.Bl=wl;p.ldb=640;
      p.M=NTOK;p.N=640;p.K=640; p.C=pX;p.ldc=640; p.bias=conv1_b; runG(p); }
    // self-attention
    layernorm_hl<<<NTOK,256>>>(pX, ln1_s, ln1_b, t1h, t1l);
    { GP p=mkgp(); p.Ah=t1h;p.Al=t1l;p.lda=640; p.Bh=wh+409600;p.Bl=wl+409600;p.ldb=640;
      p.M=NTOK;p.N=1920;p.K=640; p.Ch=q2h;p.Cl=q2l;p.ldc=1920; runG(p); }
    flash_sa<<<dim3(8,64),256,SA_SMEM>>>(q2h, q2l, t2h, t2l);
    { GP p=mkgp(); p.Ah=t2h;p.Al=t2l;p.lda=640; p.Bh=wh+1638400;p.Bl=wl+1638400;p.ldb=640;
      p.M=NTOK;p.N=640;p.K=640; p.C=pX;p.ldc=640; p.bias=sa_out_b; p.res=pX; runG(p); }
    // cross-attention
    layernorm_hl<<<NTOK,256>>>(pX, ln2_s, ln2_b, t1h, t1l);
    { GP p=mkgp(); p.Ah=t1h;p.Al=t1l;p.lda=640; p.Bh=wh+2048000;p.Bl=wl+2048000;p.ldb=640;
      p.M=NTOK;p.N=640;p.K=640; p.Ch=q2h;p.Cl=q2l;p.ldc=640; runG(p); }
    { GP p=mkgp(); p.Ah=cxh;p.Al=cxl;p.lda=512; p.Bh=wh+2457600;p.Bl=wl+2457600;p.ldb=512;
      p.M=8*SCTX;p.N=640;p.K=512; p.Ch=ckh;p.Cl=ckl;p.ldc=640; runG(p); }
    { GP p=mkgp(); p.Ah=cxh;p.Al=cxl;p.lda=512; p.Bh=wh+2785280;p.Bl=wl+2785280;p.ldb=512;
      p.M=8*SCTX;p.N=640;p.K=512; p.Ch=cvh;p.Cl=cvl;p.ldc=640; runG(p); }
    flash_ca<<<dim3(8,64),256,CA_SMEM>>>(q2h, q2l, ckh, ckl, cvh, cvl, t1h, t1l);
    { GP p=mkgp(); p.Ah=t1h;p.Al=t1l;p.lda=640; p.Bh=wh+3112960;p.Bl=wl+3112960;p.ldb=640;
      p.M=NTOK;p.N=640;p.K=640; p.C=pX;p.ldc=640; p.bias=ca_out_b; p.res=pX; runG(p); }
    // GeGLU FFN
    layernorm_hl<<<NTOK,256>>>(pX, ln3_s, ln3_b, t1h, t1l);
    { GP p=mkgp(); p.Ah=t1h;p.Al=t1l;p.lda=640; p.Bh=wh+3522560;p.Bl=wl+3522560;p.ldb=640;
      p.M=NTOK;p.N=5120;p.K=640; p.C=pF;p.ldc=5120; p.bias=lin1_b; runG(p); }
    geglu_hl<<<81920,256>>>(pF, t2h, t2l);
    { GP p=mkgp(); p.Ah=t2h;p.Al=t2l;p.lda=2560; p.Bh=wh+6799360;p.Bl=wl+6799360;p.ldb=2560;
      p.M=NTOK;p.N=640;p.K=2560; p.C=pX;p.ldc=640; p.bias=lin2_b; p.res=pX;
      p.Ch=t1h;p.Cl=t1l; runG(p); }
    // final conv + long residual (permuted NCHW)
    { GP p=mkgp(); p.Ah=t1h;p.Al=t1l;p.lda=640; p.Bh=wh+8437760;p.Bl=wl+8437760;p.ldb=640;
      p.M=NTOK;p.N=640;p.K=640; p.C=out;p.ldc=640; p.bias=co_b; p.res=x; p.permute=1; runG(p); }
}